// round 15
// baseline (speedup 1.0000x reference)
#include <cuda_runtime.h>
#include <cuda.h>
#include <cuda_bf16.h>
#include <math.h>
#include <stdint.h>

#define B_ 8
#define T_ 128
#define E_ 30522
#define H_ 1000
#define S_ 64
#define NZ_ 10000
#define G4_ 4000
#define EN_ 40522

#define KP1 30528
#define KP3 10048
#define KP6 1024

// ---------------- bf16 hi/lo operand buffers (zero-init; pads stay zero) ----------------
__device__ __align__(128) __nv_bfloat16 cAx_h[(size_t)1024 * KP1],  cAx_l[(size_t)1024 * KP1];
__device__ __align__(128) __nv_bfloat16 cWih_h[(size_t)4096 * KP1], cWih_l[(size_t)4096 * KP1];
__device__ __align__(128) __nv_bfloat16 cEmb1_h[(size_t)1024 * KP1], cEmb1_l[(size_t)1024 * KP1];
__device__ __align__(128) __nv_bfloat16 cB2_h[(size_t)1280 * KP1],  cB2_l[(size_t)1280 * KP1];
__device__ __align__(128) __nv_bfloat16 cN1_h[(size_t)512 * KP3],   cN1_l[(size_t)512 * KP3];
__device__ __align__(128) __nv_bfloat16 cEmb2_h[(size_t)1024 * KP3], cEmb2_l[(size_t)1024 * KP3];
__device__ __align__(128) __nv_bfloat16 cOutW_h[(size_t)30720 * KP6], cOutW_l[(size_t)30720 * KP6];
__device__ __align__(128) __nv_bfloat16 cHS_h[(size_t)512 * KP6],   cHS_l[(size_t)512 * KP6];

// ---------------- fp32 scratch ----------------
__device__ float g_encx[(size_t)T_ * B_ * G4_];
__device__ float g_M2[(size_t)H_ * 1033];
__device__ float g_pre[S_ * B_ * H_];
__device__ float g_part[(size_t)8 * 1024 * 4000];   // split-K partials (max: GEMM1 z=8)
__device__ float g_encout[(size_t)T_ * B_ * H_];
__device__ float g_c[B_ * H_];
__device__ float g_emb[B_ * H_];
__device__ float g_logit[B_ * T_];
__device__ float g_applied[B_ * H_];
__device__ float g_comb[B_ * H_];
__device__ float g_HS[(size_t)S_ * B_ * H_];

__device__ unsigned g_barCnt = 0;
__device__ volatile unsigned g_barPhase = 0;

// ---------------- helpers ----------------
__device__ __forceinline__ float wsum(float v) {
#pragma unroll
    for (int o = 16; o; o >>= 1) v += __shfl_xor_sync(0xffffffffu, v, o);
    return v;
}
__device__ __forceinline__ float sigf(float x) { return 1.f / (1.f + expf(-x)); }
__device__ __forceinline__ uint32_t smem_u32(const void* p) {
    uint32_t a;
    asm("{ .reg .u64 t; cvta.to.shared.u64 t, %1; cvt.u32.u64 %0, t; }" : "=r"(a) : "l"(p));
    return a;
}
#define MBAR_INIT(a, n) asm volatile("mbarrier.init.shared.b64 [%0], %1;" :: "r"(a), "r"(n) : "memory")
#define MBAR_EXPECT_TX(a, b) asm volatile("mbarrier.arrive.expect_tx.shared.b64 _, [%0], %1;" :: "r"(a), "r"(b) : "memory")
#define MBAR_WAIT(a, par) do { \
    asm volatile("{\n\t.reg .pred P1;\n\tWL_%=:\n\t" \
        "mbarrier.try_wait.parity.acquire.cta.shared::cta.b64 P1, [%0], %1, 0x989680;\n\t" \
        "@P1 bra.uni WD_%=;\n\tbra.uni WL_%=;\n\tWD_%=:\n\t}" \
        :: "r"(a), "r"(par) : "memory"); } while (0)
#define FENCE_ASYNC() asm volatile("fence.proxy.async.shared::cta;" ::: "memory")
#define TMA2D(dst, map, cx, cy, mbar) \
    asm volatile("cp.async.bulk.tensor.2d.shared::cta.global.tile.mbarrier::complete_tx::bytes " \
                 "[%0], [%1, {%2, %3}], [%4];" \
                 :: "r"(dst), "l"(map), "r"(cx), "r"(cy), "r"(mbar) : "memory")
#define LDSM4(r0, r1, r2, r3, a) \
    asm volatile("ldmatrix.sync.aligned.m8n8.x4.shared.b16 {%0,%1,%2,%3}, [%4];" \
                 : "=r"(r0), "=r"(r1), "=r"(r2), "=r"(r3) : "r"(a))
__device__ __forceinline__ void mma16(float* d, const uint32_t* a, uint32_t b0, uint32_t b1) {
    asm volatile(
        "mma.sync.aligned.m16n8k16.row.col.f32.bf16.bf16.f32 "
        "{%0,%1,%2,%3}, {%4,%5,%6,%7}, {%8,%9}, {%0,%1,%2,%3};"
        : "+f"(d[0]), "+f"(d[1]), "+f"(d[2]), "+f"(d[3])
        : "r"(a[0]), "r"(a[1]), "r"(a[2]), "r"(a[3]), "r"(b0), "r"(b1));
}

__device__ __forceinline__ void grid_bar(int nCtas) {
    __threadfence();
    __syncthreads();
    if (threadIdx.x == 0) {
        unsigned ph = g_barPhase;
        if (atomicAdd(&g_barCnt, 1u) == (unsigned)(nCtas - 1)) {
            atomicExch(&g_barCnt, 0u);
            __threadfence();
            g_barPhase = ph + 1;
        } else {
            while (g_barPhase == ph) { __nanosleep(64); }
        }
        __threadfence();
    }
    __syncthreads();
}

// ---------------- TMA + mma.sync GEMM (R10 config: 256 thr) ----------------
#define STG_B 98304
#define STG_TX 98304u
#define GSMEM (1024 + 2 * STG_B)

__global__ __launch_bounds__(256) void mma_gemm_tma(
    const __grid_constant__ CUtensorMap mAh, const __grid_constant__ CUtensorMap mAl,
    const __grid_constant__ CUtensorMap mBh, const __grid_constant__ CUtensorMap mBl,
    const float* __restrict__ bias1, const float* __restrict__ bias2,
    float* __restrict__ C, int M, int N, int ldc,
    int nch, int cpp, long long partStride, int mOff)
{
    extern __shared__ __align__(128) char smem[];
    __shared__ __align__(16) uint64_t mbars[2];
    uint32_t sb = (smem_u32(smem) + 1023u) & ~1023u;
    uint32_t mb0 = smem_u32(&mbars[0]);
    int tid = threadIdx.x, wid = tid >> 5, lane = tid & 31;
    int moff = (wid >> 1) * 32, noff = (wid & 1) * 128;
    int mBase = mOff + blockIdx.y * 128, nBase = blockIdx.x * 256;
    int z = blockIdx.z;
    int c0 = z * cpp;
    int c1 = c0 + cpp; if (c1 > nch) c1 = nch;
    float* Cw = C + (size_t)z * (size_t)partStride;

    if (tid == 0) {
        MBAR_INIT(mb0, 1);
        MBAR_INIT(mb0 + 8, 1);
        FENCE_ASYNC();
    }
    __syncthreads();

    float acc[2][16][4];
#pragma unroll
    for (int i = 0; i < 2; i++)
#pragma unroll
        for (int j = 0; j < 16; j++)
#pragma unroll
            for (int c = 0; c < 4; c++) acc[i][j][c] = 0.f;

    auto issue = [&](int st, int c) {
        uint32_t s0 = sb + st * STG_B;
        uint32_t mb = mb0 + st * 8;
        int kx = c * 64;
        MBAR_EXPECT_TX(mb, STG_TX);
        TMA2D(s0,          &mAh, kx, mBase, mb);
        TMA2D(s0 + 16384,  &mAl, kx, mBase, mb);
        TMA2D(s0 + 32768,  &mBh, kx, nBase, mb);
        TMA2D(s0 + 65536,  &mBl, kx, nBase, mb);
    };

    if (tid == 0) {
        issue(0, c0);
        if (c0 + 1 < c1) issue(1, c0 + 1);
    }

    int arow0 = moff + (lane & 15);
    int ahalf = lane >> 4;
    int bsel = (lane & 7) | (((lane >> 4) & 1) << 3);
    int bhalf = (lane >> 3) & 1;

    for (int c = c0; c < c1; c++) {
        int st = (c - c0) & 1;
        int ph = ((c - c0) >> 1) & 1;
        MBAR_WAIT(mb0 + st * 8, ph);

        uint32_t s0 = sb + st * STG_B;
        uint32_t Ab = s0, Bb = s0 + 32768;
#pragma unroll
        for (int h = 0; h < 4; h++) {
            uint32_t aH0[4], aH1[4], aL0[4], aL1[4];
            {
                int r0 = arow0, r1 = arow0 + 16;
                uint32_t c0a = ((uint32_t)((2 * h + ahalf) ^ (r0 & 7))) << 4;
                uint32_t c1a = ((uint32_t)((2 * h + ahalf) ^ (r1 & 7))) << 4;
                uint32_t a0 = Ab + r0 * 128 + c0a;
                uint32_t a1 = Ab + r1 * 128 + c1a;
                LDSM4(aH0[0], aH0[1], aH0[2], aH0[3], a0);
                LDSM4(aH1[0], aH1[1], aH1[2], aH1[3], a1);
                LDSM4(aL0[0], aL0[1], aL0[2], aL0[3], a0 + 16384);
                LDSM4(aL1[0], aL1[1], aL1[2], aL1[3], a1 + 16384);
            }
#pragma unroll
            for (int p = 0; p < 8; p++) {
                int br = noff + p * 16 + bsel;
                uint32_t bc = ((uint32_t)((2 * h + bhalf) ^ (br & 7))) << 4;
                uint32_t ba = Bb + br * 128 + bc;
                uint32_t bH[4], bL[4];
                LDSM4(bH[0], bH[1], bH[2], bH[3], ba);
                LDSM4(bL[0], bL[1], bL[2], bL[3], ba + 32768);
                mma16(acc[0][2 * p],     aH0, bH[0], bH[1]);
                mma16(acc[0][2 * p + 1], aH0, bH[2], bH[3]);
                mma16(acc[1][2 * p],     aH1, bH[0], bH[1]);
                mma16(acc[1][2 * p + 1], aH1, bH[2], bH[3]);
                mma16(acc[0][2 * p],     aH0, bL[0], bL[1]);
                mma16(acc[0][2 * p + 1], aH0, bL[2], bL[3]);
                mma16(acc[1][2 * p],     aH1, bL[0], bL[1]);
                mma16(acc[1][2 * p + 1], aH1, bL[2], bL[3]);
                mma16(acc[0][2 * p],     aL0, bH[0], bH[1]);
                mma16(acc[0][2 * p + 1], aL0, bH[2], bH[3]);
                mma16(acc[1][2 * p],     aL1, bH[0], bH[1]);
                mma16(acc[1][2 * p + 1], aL1, bH[2], bH[3]);
            }
        }
        __syncthreads();
        if (tid == 0 && c + 2 < c1) issue(st, c + 2);
    }

    int gid = lane >> 2, tig = lane & 3;
#pragma unroll
    for (int mt = 0; mt < 2; mt++)
#pragma unroll
        for (int nt = 0; nt < 16; nt++)
#pragma unroll
            for (int cc = 0; cc < 4; cc++) {
                int row = mBase + moff + mt * 16 + gid + ((cc >> 1) ? 8 : 0);
                int col = nBase + noff + nt * 8 + tig * 2 + (cc & 1);
                if (row < M && col < N) {
                    float v = acc[mt][nt][cc];
                    if (bias1) v += bias1[col];
                    if (bias2) v += bias2[col];
                    Cw[(size_t)row * ldc + col] = v;
                }
            }
}

// ---------------- split-K reduction (two optional biases) ----------------
__global__ void reduce_parts(const float* __restrict__ part, float* __restrict__ dst,
                             const float* __restrict__ bias1, const float* __restrict__ bias2,
                             int M, int N, int nparts) {
    int i = blockIdx.x * 256 + threadIdx.x;
    if (i >= M * N) return;
    size_t stride = (size_t)M * N;
    float s = 0.f;
    for (int z = 0; z < nparts; z++) s += part[z * stride + i];
    if (bias1) s += bias1[i % N];
    if (bias2) s += bias2[i % N];
    dst[i] = s;
}

// ---------------- conversion kernels ----------------
__global__ void conv_pair8(const float* __restrict__ src, int srcLd, int encmap,
                           __nv_bfloat16* __restrict__ dh, __nv_bfloat16* __restrict__ dl,
                           int K, int Kpad) {
    int k0 = (blockIdx.x * 256 + threadIdx.x) * 8;
    int r = blockIdx.y;
    if (k0 >= Kpad) return;
    size_t so;
    if (encmap) { int t = r >> 3, b = r & 7; so = ((size_t)b * T_ + t) * (size_t)srcLd; }
    else so = (size_t)r * (size_t)srcLd;
    uint32_t hw[4], lw[4];
#pragma unroll
    for (int jj = 0; jj < 4; jj++) {
        float v0 = (k0 + 2 * jj     < K) ? src[so + k0 + 2 * jj]     : 0.f;
        float v1 = (k0 + 2 * jj + 1 < K) ? src[so + k0 + 2 * jj + 1] : 0.f;
        __nv_bfloat16 h0 = __float2bfloat16_rn(v0);
        __nv_bfloat16 h1 = __float2bfloat16_rn(v1);
        __nv_bfloat16 l0 = __float2bfloat16_rn(v0 - __bfloat162float(h0));
        __nv_bfloat16 l1 = __float2bfloat16_rn(v1 - __bfloat162float(h1));
        hw[jj] = ((uint32_t)__bfloat16_as_ushort(h1) << 16) | __bfloat16_as_ushort(h0);
        lw[jj] = ((uint32_t)__bfloat16_as_ushort(l1) << 16) | __bfloat16_as_ushort(l0);
    }
    size_t doff = (size_t)r * Kpad + k0;
    *reinterpret_cast<uint4*>(dh + doff) = make_uint4(hw[0], hw[1], hw[2], hw[3]);
    *reinterpret_cast<uint4*>(dl + doff) = make_uint4(lw[0], lw[1], lw[2], lw[3]);
}

__global__ void conv_trans(const float* __restrict__ src, int srcRows, int srcCols,
                           __nv_bfloat16* __restrict__ dh, __nv_bfloat16* __restrict__ dl,
                           int dstRows, int Kpad) {
    __shared__ float t[32][33];
    int e0 = blockIdx.x * 32, h0 = blockIdx.y * 32;
    int tx = threadIdx.x, ty = threadIdx.y;
    for (int i = ty; i < 32; i += 8) {
        int e = e0 + i, h = h0 + tx;
        t[i][tx] = (e < srcRows && h < srcCols) ? src[(size_t)e * srcCols + h] : 0.f;
    }
    __syncthreads();
    for (int i = ty; i < 32; i += 8) {
        int h = h0 + i, e = e0 + tx;
        if (h < dstRows && e < Kpad) {
            float v = t[tx][i];
            __nv_bfloat16 hh = __float2bfloat16_rn(v);
            dh[(size_t)h * Kpad + e] = hh;
            dl[(size_t)h * Kpad + e] = __float2bfloat16_rn(v - __bfloat162float(hh));
        }
    }
}

// ---------------- encoder (persistent) + decoder (per-step launches) ----------------
__global__ void zero_c() {
    int i = blockIdx.x * blockDim.x + threadIdx.x;
    if (i < B_ * H_) g_c[i] = 0.f;
}

__global__ __launch_bounds__(256) void enc_scan(const float* __restrict__ Whh) {
    __shared__ float hs[8][H_];
    int tid = threadIdx.x;
    int w = tid >> 5, lane = tid & 31;
    int j = blockIdx.x * 8 + w;
    const float* w0 = Whh + (size_t)(0 * H_ + j) * H_;
    const float* w1 = Whh + (size_t)(1 * H_ + j) * H_;
    const float* w2 = Whh + (size_t)(2 * H_ + j) * H_;
    const float* w3 = Whh + (size_t)(3 * H_ + j) * H_;
    for (int t = 0; t < T_; t++) {
        for (int b = 0; b < 8; b++)
            for (int k = tid; k < H_; k += 256)
                hs[b][k] = (t == 0) ? 0.f : g_encout[((size_t)(t - 1) * 8 + b) * H_ + k];
        __syncthreads();
        float a[4][8];
#pragma unroll
        for (int g = 0; g < 4; g++)
#pragma unroll
            for (int b = 0; b < 8; b++) a[g][b] = 0.f;
        for (int k = lane; k < H_; k += 32) {
            float x0 = w0[k], x1 = w1[k], x2 = w2[k], x3 = w3[k];
#pragma unroll
            for (int b = 0; b < 8; b++) {
                float h = hs[b][k];
                a[0][b] += x0 * h; a[1][b] += x1 * h; a[2][b] += x2 * h; a[3][b] += x3 * h;
            }
        }
#pragma unroll
        for (int g = 0; g < 4; g++)
#pragma unroll
            for (int b = 0; b < 8; b++) a[g][b] = wsum(a[g][b]);
        if (lane == 0) {
#pragma unroll
            for (int b = 0; b < 8; b++) {
                const float* ex = &g_encx[((size_t)t * 8 + b) * G4_];
                float gi = sigf(a[0][b] + ex[j]);
                float gf = sigf(a[1][b] + ex[H_ + j]);
                float gg = tanhf(a[2][b] + ex[2 * H_ + j]);
                float go = sigf(a[3][b] + ex[3 * H_ + j]);
                float c = gf * g_c[b * H_ + j] + gi * gg;
                g_c[b * H_ + j] = c;
                g_encout[((size_t)t * 8 + b) * H_ + j] = go * tanhf(c);
            }
        }
        grid_bar(125);
    }
}

__global__ __launch_bounds__(256) void dec_emb2(int s) {
    __shared__ float hs[8][H_];
    int tid = threadIdx.x;
    if (s > 0) {
        for (int b = 0; b < 8; b++)
            for (int k = tid; k < H_; k += 256)
                hs[b][k] = g_HS[((size_t)(s - 1) * 8 + b) * H_ + k];
        __syncthreads();
    }
    int w = tid >> 5, lane = tid & 31;
    int j = blockIdx.x * 8 + w;
    float a[8];
#pragma unroll
    for (int b = 0; b < 8; b++) a[b] = 0.f;
    if (s > 0) {
        const float* m = &g_M2[(size_t)j * 1033];
        for (int k = lane; k < H_; k += 32) {
            float mv = m[k];
#pragma unroll
            for (int b = 0; b < 8; b++) a[b] += mv * hs[b][k];
        }
    }
#pragma unroll
    for (int b = 0; b < 8; b++) a[b] = wsum(a[b]);
    if (lane == 0) {
#pragma unroll
        for (int b = 0; b < 8; b++) {
            float v = g_pre[((size_t)s * 8 + b) * H_ + j];
            if (s == 0) v += g_M2[(size_t)j * 1033 + 1024 + b];
            else v += a[b] + g_M2[(size_t)j * 1033 + 1032];
            g_emb[b * H_ + j] = v;
        }
    }
}

__global__ __launch_bounds__(256) void dec_attn2(int s, const float* __restrict__ attn_W,
                                                 const float* __restrict__ attn_b,
                                                 const float* __restrict__ noise2) {
    extern __shared__ float vs[];
    int tid = threadIdx.x;
    for (int b = 0; b < 8; b++) {
        const float* hp = (s == 0) ? &g_encout[((size_t)(T_ - 1) * 8 + b) * H_]
                                   : &g_HS[((size_t)(s - 1) * 8 + b) * H_];
        const float* n2 = noise2 + ((size_t)s * 8 + b) * H_;
        float* vb = vs + b * 3000;
        for (int k = tid; k < H_; k += 256) {
            vb[k] = g_emb[b * H_ + k];
            vb[H_ + k] = hp[k];
            vb[2 * H_ + k] = n2[k];
        }
    }
    __syncthreads();
    int w = tid >> 5, lane = tid & 31;
    int t = blockIdx.x * 8 + w;
    const float* wr = attn_W + (size_t)t * 3 * H_;
    float a[8];
#pragma unroll
    for (int b = 0; b < 8; b++) a[b] = 0.f;
    for (int k = lane; k < 3 * H_; k += 32) {
        float wv = wr[k];
#pragma unroll
        for (int b = 0; b < 8; b++) a[b] += wv * vs[b * 3000 + k];
    }
#pragma unroll
    for (int b = 0; b < 8; b++) a[b] = wsum(a[b]);
    if (lane == 0) {
        float ab = attn_b[t];
#pragma unroll
        for (int b = 0; b < 8; b++) g_logit[b * T_ + t] = a[b] + ab;
    }
}

__global__ void dec_soft() {
    __shared__ float aw[T_];
    __shared__ float red[8];
    int b = blockIdx.x, tid = threadIdx.x;
    int w = tid >> 5, lane = tid & 31;
    float l = (tid < T_) ? g_logit[b * T_ + tid] : -1e30f;
    float m = l;
#pragma unroll
    for (int o = 16; o; o >>= 1) m = fmaxf(m, __shfl_xor_sync(0xffffffffu, m, o));
    if (lane == 0) red[w] = m;
    __syncthreads();
    if (tid == 0) {
        float mm = red[0];
        for (int i = 1; i < 8; i++) mm = fmaxf(mm, red[i]);
        red[0] = mm;
    }
    __syncthreads();
    float mx = red[0];
    float e = (tid < T_) ? expf(l - mx) : 0.f;
    float ss = wsum(e);
    __syncthreads();
    if (lane == 0) red[w] = ss;
    __syncthreads();
    if (tid == 0) {
        float t2 = 0;
        for (int i = 0; i < 8; i++) t2 += red[i];
        red[0] = t2;
    }
    __syncthreads();
    float inv = 1.f / red[0];
    if (tid < T_) aw[tid] = e * inv;
    __syncthreads();
    for (int i = tid; i < H_; i += 256) {
        float acc = 0.f;
#pragma unroll 4
        for (int t = 0; t < T_; t++) acc += aw[t] * g_encout[((size_t)t * 8 + b) * H_ + i];
        g_applied[b * H_ + i] = acc;
    }
}

__global__ __launch_bounds__(256) void dec_comb2(const float* __restrict__ comb_W,
                                                 const float* __restrict__ comb_b) {
    extern __shared__ float sm[];
    float* es = sm;
    float* ap = sm + 8 * H_;
    int tid = threadIdx.x;
    for (int b = 0; b < 8; b++)
        for (int k = tid; k < H_; k += 256) {
            es[b * H_ + k] = g_emb[b * H_ + k];
            ap[b * H_ + k] = g_applied[b * H_ + k];
        }
    __syncthreads();
    int w = tid >> 5, lane = tid & 31;
    int i = blockIdx.x * 8 + w;
    const float* wr = comb_W + (size_t)i * 2 * H_;
    float a[8];
#pragma unroll
    for (int b = 0; b < 8; b++) a[b] = 0.f;
    for (int k = lane; k < H_; k += 32) {
        float w1 = wr[k], w2 = wr[H_ + k];
#pragma unroll
        for (int b = 0; b < 8; b++) a[b] += es[b * H_ + k] * w1 + ap[b * H_ + k] * w2;
    }
#pragma unroll
    for (int b = 0; b < 8; b++) a[b] = wsum(a[b]);
    if (lane == 0) {
        float cb = comb_b[i];
#pragma unroll
        for (int b = 0; b < 8; b++) g_comb[b * H_ + i] = fmaxf(a[b] + cb, 0.f);
    }
}

__global__ __launch_bounds__(256) void dec_lstm2(int s, const float* __restrict__ Wih,
                                                 const float* __restrict__ Whh,
                                                 const float* __restrict__ bih,
                                                 const float* __restrict__ bhh) {
    extern __shared__ float sm[];
    float* xs = sm;
    float* hs = sm + 8 * H_;
    int tid = threadIdx.x;
    for (int b = 0; b < 8; b++) {
        const float* hp = (s == 0) ? &g_encout[((size_t)(T_ - 1) * 8 + b) * H_]
                                   : &g_HS[((size_t)(s - 1) * 8 + b) * H_];
        for (int k = tid; k < H_; k += 256) {
            xs[b * H_ + k] = g_comb[b * H_ + k];
            hs[b * H_ + k] = hp[k];
        }
    }
    __syncthreads();
    int w = tid >> 5, lane = tid & 31;
    int j = blockIdx.x * 8 + w;
    const float* wi0 = Wih + (size_t)(0 * H_ + j) * H_;
    const float* wi1 = Wih + (size_t)(1 * H_ + j) * H_;
    const float* wi2 = Wih + (size_t)(2 * H_ + j) * H_;
    const float* wi3 = Wih + (size_t)(3 * H_ + j) * H_;
    const float* wh0 = Whh + (size_t)(0 * H_ + j) * H_;
    const float* wh1 = Whh + (size_t)(1 * H_ + j) * H_;
    const float* wh2 = Whh + (size_t)(2 * H_ + j) * H_;
    const float* wh3 = Whh + (size_t)(3 * H_ + j) * H_;
    float a[4][8];
#pragma unroll
    for (int g = 0; g < 4; g++)
#pragma unroll
        for (int b = 0; b < 8; b++) a[g][b] = 0.f;
    for (int k = lane; k < H_; k += 32) {
        float i0 = wi0[k], i1 = wi1[k], i2 = wi2[k], i3 = wi3[k];
        float h0 = wh0[k], h1 = wh1[k], h2 = wh2[k], h3 = wh3[k];
#pragma unroll
        for (int b = 0; b < 8; b++) {
            float x = xs[b * H_ + k], h = hs[b * H_ + k];
            a[0][b] += i0 * x + h0 * h;
            a[1][b] += i1 * x + h1 * h;
            a[2][b] += i2 * x + h2 * h;
            a[3][b] += i3 * x + h3 * h;
        }
    }
#pragma unroll
    for (int g = 0; g < 4; g++)
#pragma unroll
        for (int b = 0; b < 8; b++) a[g][b] = wsum(a[g][b]);
    if (lane == 0) {
        float b0 = bih[j] + bhh[j];
        float b1 = bih[H_ + j] + bhh[H_ + j];
        float b2 = bih[2 * H_ + j] + bhh[2 * H_ + j];
        float b3 = bih[3 * H_ + j] + bhh[3 * H_ + j];
#pragma unroll
        for (int b = 0; b < 8; b++) {
            float gi = sigf(a[0][b] + b0);
            float gf = sigf(a[1][b] + b1);
            float gg = tanhf(a[2][b] + b2);
            float go = sigf(a[3][b] + b3);
            float c = gf * g_c[b * H_ + j] + gi * gg;
            g_c[b * H_ + j] = c;
            g_HS[((size_t)s * 8 + b) * H_ + j] = go * tanhf(c);
        }
    }
}

// ---------------- host: tensormap building ----------------
typedef CUresult (*EncFn)(CUtensorMap*, CUtensorMapDataType, cuuint32_t, void*,
                          const cuuint64_t*, const cuuint64_t*, const cuuint32_t*,
                          const cuuint32_t*, CUtensorMapInterleave, CUtensorMapSwizzle,
                          CUtensorMapL2promotion, CUtensorMapFloatOOBfill);
static EncFn enc_fn() {
    static EncFn fn = nullptr;
    if (!fn) {
        void* p = nullptr;
        cudaDriverEntryPointQueryResult st;
        cudaError_t e = cudaGetDriverEntryPoint("cuTensorMapEncodeTiled", &p,
                                                cudaEnableDefault, &st);
        if (e == cudaSuccess && st == cudaDriverEntryPointSuccess) fn = (EncFn)p;
    }
    return fn;
}
static void mkmap(CUtensorMap* m, void* ptr, uint64_t kpad, uint64_t rows, uint32_t boxRows) {
    cuuint64_t dims[2] = {kpad, rows};
    cuuint64_t strides[1] = {kpad * 2};
    cuuint32_t box[2] = {64u, boxRows};
    cuuint32_t es[2] = {1u, 1u};
    EncFn f = enc_fn();
    if (!f) return;
    f(m, CU_TENSOR_MAP_DATA_TYPE_BFLOAT16, 2, ptr, dims, strides, box, es,
      CU_TENSOR_MAP_INTERLEAVE_NONE, CU_TENSOR_MAP_SWIZZLE_128B,
      CU_TENSOR_MAP_L2_PROMOTION_L2_128B, CU_TENSOR_MAP_FLOAT_OOB_FILL_NONE);
}

// ---------------- launch ----------------
extern "C" void kernel_launch(void* const* d_in, const int* in_sizes, int n_in,
                              void* d_out, int out_size) {
    const float* input   = (const float*)d_in[0];
    const float* noise1  = (const float*)d_in[2];
    const float* noise2  = (const float*)d_in[3];
    const float* initdec = (const float*)d_in[4];
    const float* eWih = (const float*)d_in[5];
    const float* eWhh = (const float*)d_in[6];
    const float* ebih = (const float*)d_in[7];
    const float* ebhh = (const float*)d_in[8];
    const float* dWih = (const float*)d_in[9];
    const float* dWhh = (const float*)d_in[10];
    const float* dbih = (const float*)d_in[11];
    const float* dbhh = (const float*)d_in[12];
    const float* embW = (const float*)d_in[13];
    const float* embb = (const float*)d_in[14];
    const float* attnW = (const float*)d_in[15];
    const float* attnb = (const float*)d_in[16];
    const float* combW = (const float*)d_in[17];
    const float* combb = (const float*)d_in[18];
    const float* outW = (const float*)d_in[19];
    const float* outb = (const float*)d_in[20];
    float* out = (float*)d_out;

    cudaFuncSetAttribute(mma_gemm_tma, cudaFuncAttributeMaxDynamicSharedMemorySize, GSMEM);
    cudaFuncSetAttribute(dec_attn2, cudaFuncAttributeMaxDynamicSharedMemorySize, 96000);
    cudaFuncSetAttribute(dec_comb2, cudaFuncAttributeMaxDynamicSharedMemorySize, 64000);
    cudaFuncSetAttribute(dec_lstm2, cudaFuncAttributeMaxDynamicSharedMemorySize, 64000);

    float *p_encx, *p_pre, *p_HS, *p_M2, *p_part;
    cudaGetSymbolAddress((void**)&p_encx, g_encx);
    cudaGetSymbolAddress((void**)&p_pre, g_pre);
    cudaGetSymbolAddress((void**)&p_HS, g_HS);
    cudaGetSymbolAddress((void**)&p_M2, g_M2);
    cudaGetSymbolAddress((void**)&p_part, g_part);
    __nv_bfloat16 *pAx_h, *pAx_l, *pWih_h, *pWih_l, *pEmb1_h, *pEmb1_l, *pB2_h, *pB2_l;
    __nv_bfloat16 *pN1_h, *pN1_l, *pEmb2_h, *pEmb2_l, *pOutW_h, *pOutW_l, *pHS_h, *pHS_l;
    cudaGetSymbolAddress((void**)&pAx_h, cAx_h);   cudaGetSymbolAddress((void**)&pAx_l, cAx_l);
    cudaGetSymbolAddress((void**)&pWih_h, cWih_h); cudaGetSymbolAddress((void**)&pWih_l, cWih_l);
    cudaGetSymbolAddress((void**)&pEmb1_h, cEmb1_h); cudaGetSymbolAddress((void**)&pEmb1_l, cEmb1_l);
    cudaGetSymbolAddress((void**)&pB2_h, cB2_h);   cudaGetSymbolAddress((void**)&pB2_l, cB2_l);
    cudaGetSymbolAddress((void**)&pN1_h, cN1_h);   cudaGetSymbolAddress((void**)&pN1_l, cN1_l);
    cudaGetSymbolAddress((void**)&pEmb2_h, cEmb2_h); cudaGetSymbolAddress((void**)&pEmb2_l, cEmb2_l);
    cudaGetSymbolAddress((void**)&pOutW_h, cOutW_h); cudaGetSymbolAddress((void**)&pOutW_l, cOutW_l);
    cudaGetSymbolAddress((void**)&pHS_h, cHS_h);   cudaGetSymbolAddress((void**)&pHS_l, cHS_l);

    CUtensorMap mAxh, mAxl, mWihh, mWihl, mE1h, mE1l, mB2h, mB2l;
    CUtensorMap mN1h, mN1l, mE2h, mE2l, mOWh, mOWl, mHSh, mHSl;
    mkmap(&mAxh, pAx_h, KP1, 1024, 128);   mkmap(&mAxl, pAx_l, KP1, 1024, 128);
    mkmap(&mWihh, pWih_h, KP1, 4000, 256); mkmap(&mWihl, pWih_l, KP1, 4000, 256);
    mkmap(&mE1h, pEmb1_h, KP1, 1000, 128); mkmap(&mE1l, pEmb1_l, KP1, 1000, 128);
    mkmap(&mB2h, pB2_h, KP1, 1033, 256);   mkmap(&mB2l, pB2_l, KP1, 1033, 256);
    mkmap(&mN1h, pN1_h, KP3, 512, 128);    mkmap(&mN1l, pN1_l, KP3, 512, 128);
    mkmap(&mE2h, pEmb2_h, KP3, 1000, 256); mkmap(&mE2l, pEmb2_l, KP3, 1000, 256);
    mkmap(&mOWh, pOutW_h, KP6, 30522, 256); mkmap(&mOWl, pOutW_l, KP6, 30522, 256);
    mkmap(&mHSh, pHS_h, KP6, 512, 128);    mkmap(&mHSl, pHS_l, KP6, 512, 128);

    int g1 = (KP1 / 8 + 255) / 256;
    int g3 = (KP3 / 8 + 255) / 256;
    int g6 = (KP6 / 8 + 255) / 256;

    // my-index 3 = GEMM1 (ncu +2 offset lands here)
    conv_pair8<<<dim3(g1, 1024), 256>>>(input, E_, 1, pAx_h, pAx_l, E_, KP1);          // 0
    conv_pair8<<<dim3(g1, 4000), 256>>>(eWih, E_, 0, pWih_h, pWih_l, E_, KP1);         // 1
    zero_c<<<(B_ * H_ + 255) / 256, 256>>>();                                          // 2
    // GEMM1 split-K=8 (1024 CTAs ~ 6.9 waves), biases applied in reduce
    mma_gemm_tma<<<dim3(16, 8, 8), 256, GSMEM>>>(mAxh, mAxl, mWihh, mWihl,             // 3: GEMM1
        nullptr, nullptr, p_part, 1024, G4_, G4_, KP1 / 64, 60, (long long)1024 * G4_, 0);
    reduce_parts<<<(1024 * G4_ + 255) / 256, 256>>>(p_part, p_encx, ebih, ebhh, 1024, G4_, 8);

    conv_pair8<<<dim3(g1, 1000), 256>>>(embW, EN_, 0, pEmb1_h, pEmb1_l, E_, KP1);
    conv_trans<<<dim3(954, 32), dim3(32, 8)>>>(outW, E_, H_, pB2_h, pB2_l, H_, KP1);
    conv_pair8<<<dim3(g1, 8), 256>>>(initdec, E_, 0, pB2_h + (size_t)1024 * KP1, pB2_l + (size_t)1024 * KP1, E_, KP1);
    conv_pair8<<<dim3(g1, 1), 256>>>(outb, E_, 0, pB2_h + (size_t)1032 * KP1, pB2_l + (size_t)1032 * KP1, E_, KP1);
    conv_pair8<<<dim3(g3, 1000), 256>>>(embW + E_, EN_, 0, pEmb2_h, pEmb2_l, NZ_, KP3);
    conv_pair8<<<dim3(g3, 512), 256>>>(noise1, NZ_, 0, pN1_h, pN1_l, NZ_, KP3);
    conv_pair8<<<dim3(g6, 30522), 256>>>(outW, H_, 0, pOutW_h, pOutW_l, H_, KP6);

    // GEMM2 split-K=16 (320 CTAs ~ 2.2 waves)
    mma_gemm_tma<<<dim3(5, 8, 16), 256, GSMEM>>>(mE1h, mE1l, mB2h, mB2l,
        nullptr, nullptr, p_part, H_, 1033, 1033, KP1 / 64, 30, (long long)H_ * 1033, 0);
    reduce_parts<<<(H_ * 1033 + 255) / 256, 256>>>(p_part, p_M2, nullptr, nullptr, H_, 1033, 16);

    // GEMM3 split-K=8 (128 CTAs, 1 wave)
    mma_gemm_tma<<<dim3(4, 4, 8), 256, GSMEM>>>(mN1h, mN1l, mE2h, mE2l,
        nullptr, nullptr, p_part, S_ * B_, H_, H_, KP3 / 64, 20, (long long)S_ * B_ * H_, 0);
    reduce_parts<<<(S_ * B_ * H_ + 255) / 256, 256>>>(p_part, p_pre, embb, nullptr, S_ * B_, H_, 8);

    // encoder scan (persistent — full-grid phases, proven)
    enc_scan<<<125, 256>>>(eWhh);

    // decoder scan (per-step launches — R13 best config)
    for (int s = 0; s < S_; s++) {
        dec_emb2<<<125, 256>>>(s);
        dec_attn2<<<16, 256, 96000>>>(s, attnW, attnb, noise2);
        dec_soft<<<B_, 256>>>();
        dec_comb2<<<125, 256, 64000>>>(combW, combb);
        dec_lstm2<<<125, 256, 64000>>>(s, dWih, dWhh, dbih, dbhh);
    }

    // final output GEMM (480 CTAs ~ 3.2 waves)
    conv_pair8<<<dim3(g6, 512), 256>>>(p_HS, H_, 0, pHS_h, pHS_l, H_, KP6);
    mma_gemm_tma<<<dim3(120, 4, 1), 256, GSMEM>>>(mHSh, mHSl, mOWh, mOWl,
        outb, nullptr, out, S_ * B_, E_, E_, KP6 / 64, KP6 / 64, 0, 0);
}

// round 16
// speedup vs baseline: 1.3298x; 1.3298x over previous
#include <cuda_runtime.h>
#include <cuda.h>
#include <cuda_bf16.h>
#include <math.h>
#include <stdint.h>

#define B_ 8
#define T_ 128
#define E_ 30522
#define H_ 1000
#define S_ 64
#define NZ_ 10000
#define G4_ 4000
#define EN_ 40522

#define KP1 30528
#define KP3 10048
#define KP6 1024

// ---------------- bf16 hi/lo operand buffers (zero-init; pads stay zero) ----------------
__device__ __align__(128) __nv_bfloat16 cAx_h[(size_t)1024 * KP1],  cAx_l[(size_t)1024 * KP1];
__device__ __align__(128) __nv_bfloat16 cWih_h[(size_t)4096 * KP1], cWih_l[(size_t)4096 * KP1];
__device__ __align__(128) __nv_bfloat16 cEmb1_h[(size_t)1024 * KP1], cEmb1_l[(size_t)1024 * KP1];
__device__ __align__(128) __nv_bfloat16 cB2_h[(size_t)1280 * KP1],  cB2_l[(size_t)1280 * KP1];
__device__ __align__(128) __nv_bfloat16 cN1_h[(size_t)512 * KP3],   cN1_l[(size_t)512 * KP3];
__device__ __align__(128) __nv_bfloat16 cEmb2_h[(size_t)1024 * KP3], cEmb2_l[(size_t)1024 * KP3];
__device__ __align__(128) __nv_bfloat16 cOutW_h[(size_t)30720 * KP6], cOutW_l[(size_t)30720 * KP6];
__device__ __align__(128) __nv_bfloat16 cHS_h[(size_t)512 * KP6],   cHS_l[(size_t)512 * KP6];

// ---------------- fp32 scratch ----------------
__device__ float g_encx[(size_t)T_ * B_ * G4_];
__device__ float g_M2[(size_t)H_ * 1033];
__device__ float g_pre[S_ * B_ * H_];
__device__ float g_part[(size_t)8 * 1033 * 1000];
__device__ float g_encout[(size_t)T_ * B_ * H_];
__device__ float g_c[B_ * H_];
__device__ float g_emb[B_ * H_];
__device__ float g_logit[B_ * T_];
__device__ float g_applied[B_ * H_];
__device__ float g_comb[B_ * H_];
__device__ float g_HS[(size_t)S_ * B_ * H_];

__device__ unsigned g_barCnt = 0;
__device__ volatile unsigned g_barPhase = 0;

// ---------------- helpers ----------------
__device__ __forceinline__ float wsum(float v) {
#pragma unroll
    for (int o = 16; o; o >>= 1) v += __shfl_xor_sync(0xffffffffu, v, o);
    return v;
}
__device__ __forceinline__ float sigf(float x) { return 1.f / (1.f + expf(-x)); }
__device__ __forceinline__ uint32_t smem_u32(const void* p) {
    uint32_t a;
    asm("{ .reg .u64 t; cvta.to.shared.u64 t, %1; cvt.u32.u64 %0, t; }" : "=r"(a) : "l"(p));
    return a;
}
#define MBAR_INIT(a, n) asm volatile("mbarrier.init.shared.b64 [%0], %1;" :: "r"(a), "r"(n) : "memory")
#define MBAR_EXPECT_TX(a, b) asm volatile("mbarrier.arrive.expect_tx.shared.b64 _, [%0], %1;" :: "r"(a), "r"(b) : "memory")
#define MBAR_WAIT(a, par) do { \
    asm volatile("{\n\t.reg .pred P1;\n\tWL_%=:\n\t" \
        "mbarrier.try_wait.parity.acquire.cta.shared::cta.b64 P1, [%0], %1, 0x989680;\n\t" \
        "@P1 bra.uni WD_%=;\n\tbra.uni WL_%=;\n\tWD_%=:\n\t}" \
        :: "r"(a), "r"(par) : "memory"); } while (0)
#define FENCE_ASYNC() asm volatile("fence.proxy.async.shared::cta;" ::: "memory")
#define TMA2D(dst, map, cx, cy, mbar) \
    asm volatile("cp.async.bulk.tensor.2d.shared::cta.global.tile.mbarrier::complete_tx::bytes " \
                 "[%0], [%1, {%2, %3}], [%4];" \
                 :: "r"(dst), "l"(map), "r"(cx), "r"(cy), "r"(mbar) : "memory")
#define LDSM4(r0, r1, r2, r3, a) \
    asm volatile("ldmatrix.sync.aligned.m8n8.x4.shared.b16 {%0,%1,%2,%3}, [%4];" \
                 : "=r"(r0), "=r"(r1), "=r"(r2), "=r"(r3) : "r"(a))
__device__ __forceinline__ void mma16(float* d, const uint32_t* a, uint32_t b0, uint32_t b1) {
    asm volatile(
        "mma.sync.aligned.m16n8k16.row.col.f32.bf16.bf16.f32 "
        "{%0,%1,%2,%3}, {%4,%5,%6,%7}, {%8,%9}, {%0,%1,%2,%3};"
        : "+f"(d[0]), "+f"(d[1]), "+f"(d[2]), "+f"(d[3])
        : "r"(a[0]), "r"(a[1]), "r"(a[2]), "r"(a[3]), "r"(b0), "r"(b1));
}

__device__ __forceinline__ void grid_bar(int nCtas) {
    __threadfence();
    __syncthreads();
    if (threadIdx.x == 0) {
        unsigned ph = g_barPhase;
        if (atomicAdd(&g_barCnt, 1u) == (unsigned)(nCtas - 1)) {
            atomicExch(&g_barCnt, 0u);
            __threadfence();
            g_barPhase = ph + 1;
        } else {
            while (g_barPhase == ph) { __nanosleep(64); }
        }
        __threadfence();
    }
    __syncthreads();
}

// ---------------- TMA + mma.sync GEMM (proven R10 config: 256 thr) ----------------
#define STG_B 98304
#define STG_TX 98304u
#define GSMEM (1024 + 2 * STG_B)

__global__ __launch_bounds__(256) void mma_gemm_tma(
    const __grid_constant__ CUtensorMap mAh, const __grid_constant__ CUtensorMap mAl,
    const __grid_constant__ CUtensorMap mBh, const __grid_constant__ CUtensorMap mBl,
    const float* __restrict__ bias1, const float* __restrict__ bias2,
    float* __restrict__ C, int M, int N, int ldc,
    int nch, int cpp, long long partStride, int mOff)
{
    extern __shared__ __align__(128) char smem[];
    __shared__ __align__(16) uint64_t mbars[2];
    uint32_t sb = (smem_u32(smem) + 1023u) & ~1023u;
    uint32_t mb0 = smem_u32(&mbars[0]);
    int tid = threadIdx.x, wid = tid >> 5, lane = tid & 31;
    int moff = (wid >> 1) * 32, noff = (wid & 1) * 128;
    int mBase = mOff + blockIdx.y * 128, nBase = blockIdx.x * 256;
    int z = blockIdx.z;
    int c0 = z * cpp;
    int c1 = c0 + cpp; if (c1 > nch) c1 = nch;
    float* Cw = C + (size_t)z * (size_t)partStride;

    if (tid == 0) {
        MBAR_INIT(mb0, 1);
        MBAR_INIT(mb0 + 8, 1);
        FENCE_ASYNC();
    }
    __syncthreads();

    float acc[2][16][4];
#pragma unroll
    for (int i = 0; i < 2; i++)
#pragma unroll
        for (int j = 0; j < 16; j++)
#pragma unroll
            for (int c = 0; c < 4; c++) acc[i][j][c] = 0.f;

    auto issue = [&](int st, int c) {
        uint32_t s0 = sb + st * STG_B;
        uint32_t mb = mb0 + st * 8;
        int kx = c * 64;
        MBAR_EXPECT_TX(mb, STG_TX);
        TMA2D(s0,          &mAh, kx, mBase, mb);
        TMA2D(s0 + 16384,  &mAl, kx, mBase, mb);
        TMA2D(s0 + 32768,  &mBh, kx, nBase, mb);
        TMA2D(s0 + 65536,  &mBl, kx, nBase, mb);
    };

    if (tid == 0) {
        issue(0, c0);
        if (c0 + 1 < c1) issue(1, c0 + 1);
    }

    int arow0 = moff + (lane & 15);
    int ahalf = lane >> 4;
    int bsel = (lane & 7) | (((lane >> 4) & 1) << 3);
    int bhalf = (lane >> 3) & 1;

    for (int c = c0; c < c1; c++) {
        int st = (c - c0) & 1;
        int ph = ((c - c0) >> 1) & 1;
        MBAR_WAIT(mb0 + st * 8, ph);

        uint32_t s0 = sb + st * STG_B;
        uint32_t Ab = s0, Bb = s0 + 32768;
#pragma unroll
        for (int h = 0; h < 4; h++) {
            uint32_t aH0[4], aH1[4], aL0[4], aL1[4];
            {
                int r0 = arow0, r1 = arow0 + 16;
                uint32_t c0a = ((uint32_t)((2 * h + ahalf) ^ (r0 & 7))) << 4;
                uint32_t c1a = ((uint32_t)((2 * h + ahalf) ^ (r1 & 7))) << 4;
                uint32_t a0 = Ab + r0 * 128 + c0a;
                uint32_t a1 = Ab + r1 * 128 + c1a;
                LDSM4(aH0[0], aH0[1], aH0[2], aH0[3], a0);
                LDSM4(aH1[0], aH1[1], aH1[2], aH1[3], a1);
                LDSM4(aL0[0], aL0[1], aL0[2], aL0[3], a0 + 16384);
                LDSM4(aL1[0], aL1[1], aL1[2], aL1[3], a1 + 16384);
            }
#pragma unroll
            for (int p = 0; p < 8; p++) {
                int br = noff + p * 16 + bsel;
                uint32_t bc = ((uint32_t)((2 * h + bhalf) ^ (br & 7))) << 4;
                uint32_t ba = Bb + br * 128 + bc;
                uint32_t bH[4], bL[4];
                LDSM4(bH[0], bH[1], bH[2], bH[3], ba);
                LDSM4(bL[0], bL[1], bL[2], bL[3], ba + 32768);
                mma16(acc[0][2 * p],     aH0, bH[0], bH[1]);
                mma16(acc[0][2 * p + 1], aH0, bH[2], bH[3]);
                mma16(acc[1][2 * p],     aH1, bH[0], bH[1]);
                mma16(acc[1][2 * p + 1], aH1, bH[2], bH[3]);
                mma16(acc[0][2 * p],     aH0, bL[0], bL[1]);
                mma16(acc[0][2 * p + 1], aH0, bL[2], bL[3]);
                mma16(acc[1][2 * p],     aH1, bL[0], bL[1]);
                mma16(acc[1][2 * p + 1], aH1, bL[2], bL[3]);
                mma16(acc[0][2 * p],     aL0, bH[0], bH[1]);
                mma16(acc[0][2 * p + 1], aL0, bH[2], bH[3]);
                mma16(acc[1][2 * p],     aL1, bH[0], bH[1]);
                mma16(acc[1][2 * p + 1], aL1, bH[2], bH[3]);
            }
        }
        __syncthreads();
        if (tid == 0 && c + 2 < c1) issue(st, c + 2);
    }

    int gid = lane >> 2, tig = lane & 3;
#pragma unroll
    for (int mt = 0; mt < 2; mt++)
#pragma unroll
        for (int nt = 0; nt < 16; nt++)
#pragma unroll
            for (int cc = 0; cc < 4; cc++) {
                int row = mBase + moff + mt * 16 + gid + ((cc >> 1) ? 8 : 0);
                int col = nBase + noff + nt * 8 + tig * 2 + (cc & 1);
                if (row < M && col < N) {
                    float v = acc[mt][nt][cc];
                    if (bias1) v += bias1[col];
                    if (bias2) v += bias2[col];
                    Cw[(size_t)row * ldc + col] = v;
                }
            }
}

// ---------------- split-K reductions ----------------
__global__ void reduce_parts(const float* __restrict__ part, float* __restrict__ dst,
                             const float* __restrict__ bias, int M, int N, int nparts) {
    int i = blockIdx.x * 256 + threadIdx.x;
    if (i >= M * N) return;
    size_t stride = (size_t)M * N;
    float s = 0.f;
    for (int z = 0; z < nparts; z++) s += part[z * stride + i];
    if (bias) s += bias[i % N];
    dst[i] = s;
}

// reduce with destination row-stride (GEMM2 -> g_M2 1033-wide rows)
__global__ void reduce_ld(const float* __restrict__ part, float* __restrict__ dst,
                          int M, int N, int dstLd, int nparts) {
    int i = blockIdx.x * 256 + threadIdx.x;
    if (i >= M * N) return;
    size_t stride = (size_t)M * N;
    float s = 0.f;
    for (int z = 0; z < nparts; z++) s += part[z * stride + i];
    dst[(size_t)(i / N) * dstLd + (i % N)] = s;
}

// E0 and bvec columns of g_M2, exact fp32 (replaces 5th N-tile of GEMM2)
__global__ __launch_bounds__(256) void e0bvec(const float* __restrict__ embW,
                                              const float* __restrict__ initdec,
                                              const float* __restrict__ outb) {
    int w = threadIdx.x >> 5, lane = threadIdx.x & 31;
    int j = blockIdx.x * 8 + w;
    const float* row = embW + (size_t)j * EN_;
    float a[9];
#pragma unroll
    for (int i = 0; i < 9; i++) a[i] = 0.f;
    for (int k = lane; k < E_; k += 32) {
        float wv = row[k];
#pragma unroll
        for (int b = 0; b < 8; b++) a[b] += wv * initdec[(size_t)b * E_ + k];
        a[8] += wv * outb[k];
    }
#pragma unroll
    for (int i = 0; i < 9; i++) a[i] = wsum(a[i]);
    if (lane == 0) {
#pragma unroll
        for (int b = 0; b < 8; b++) g_M2[(size_t)j * 1033 + 1024 + b] = a[b];
        g_M2[(size_t)j * 1033 + 1032] = a[8];
    }
}

// ---------------- conversion kernels ----------------
__global__ void conv_pair8(const float* __restrict__ src, int srcLd, int encmap,
                           __nv_bfloat16* __restrict__ dh, __nv_bfloat16* __restrict__ dl,
                           int K, int Kpad) {
    int k0 = (blockIdx.x * 256 + threadIdx.x) * 8;
    int r = blockIdx.y;
    if (k0 >= Kpad) return;
    size_t so;
    if (encmap) { int t = r >> 3, b = r & 7; so = ((size_t)b * T_ + t) * (size_t)srcLd; }
    else so = (size_t)r * (size_t)srcLd;
    uint32_t hw[4], lw[4];
#pragma unroll
    for (int jj = 0; jj < 4; jj++) {
        float v0 = (k0 + 2 * jj     < K) ? src[so + k0 + 2 * jj]     : 0.f;
        float v1 = (k0 + 2 * jj + 1 < K) ? src[so + k0 + 2 * jj + 1] : 0.f;
        __nv_bfloat16 h0 = __float2bfloat16_rn(v0);
        __nv_bfloat16 h1 = __float2bfloat16_rn(v1);
        __nv_bfloat16 l0 = __float2bfloat16_rn(v0 - __bfloat162float(h0));
        __nv_bfloat16 l1 = __float2bfloat16_rn(v1 - __bfloat162float(h1));
        hw[jj] = ((uint32_t)__bfloat16_as_ushort(h1) << 16) | __bfloat16_as_ushort(h0);
        lw[jj] = ((uint32_t)__bfloat16_as_ushort(l1) << 16) | __bfloat16_as_ushort(l0);
    }
    size_t doff = (size_t)r * Kpad + k0;
    *reinterpret_cast<uint4*>(dh + doff) = make_uint4(hw[0], hw[1], hw[2], hw[3]);
    *reinterpret_cast<uint4*>(dl + doff) = make_uint4(lw[0], lw[1], lw[2], lw[3]);
}

__global__ void conv_trans(const float* __restrict__ src, int srcRows, int srcCols,
                           __nv_bfloat16* __restrict__ dh, __nv_bfloat16* __restrict__ dl,
                           int dstRows, int Kpad) {
    __shared__ float t[32][33];
    int e0 = blockIdx.x * 32, h0 = blockIdx.y * 32;
    int tx = threadIdx.x, ty = threadIdx.y;
    for (int i = ty; i < 32; i += 8) {
        int e = e0 + i, h = h0 + tx;
        t[i][tx] = (e < srcRows && h < srcCols) ? src[(size_t)e * srcCols + h] : 0.f;
    }
    __syncthreads();
    for (int i = ty; i < 32; i += 8) {
        int h = h0 + i, e = e0 + tx;
        if (h < dstRows && e < Kpad) {
            float v = t[tx][i];
            __nv_bfloat16 hh = __float2bfloat16_rn(v);
            dh[(size_t)h * Kpad + e] = hh;
            dl[(size_t)h * Kpad + e] = __float2bfloat16_rn(v - __bfloat162float(hh));
        }
    }
}

// ---------------- encoder (persistent) + decoder (per-step launches) ----------------
__global__ void zero_c() {
    int i = blockIdx.x * blockDim.x + threadIdx.x;
    if (i < B_ * H_) g_c[i] = 0.f;
}

__global__ __launch_bounds__(256) void enc_scan(const float* __restrict__ Whh) {
    __shared__ float hs[8][H_];
    int tid = threadIdx.x;
    int w = tid >> 5, lane = tid & 31;
    int j = blockIdx.x * 8 + w;
    const float* w0 = Whh + (size_t)(0 * H_ + j) * H_;
    const float* w1 = Whh + (size_t)(1 * H_ + j) * H_;
    const float* w2 = Whh + (size_t)(2 * H_ + j) * H_;
    const float* w3 = Whh + (size_t)(3 * H_ + j) * H_;
    for (int t = 0; t < T_; t++) {
        for (int b = 0; b < 8; b++)
            for (int k = tid; k < H_; k += 256)
                hs[b][k] = (t == 0) ? 0.f : g_encout[((size_t)(t - 1) * 8 + b) * H_ + k];
        __syncthreads();
        float a[4][8];
#pragma unroll
        for (int g = 0; g < 4; g++)
#pragma unroll
            for (int b = 0; b < 8; b++) a[g][b] = 0.f;
        for (int k = lane; k < H_; k += 32) {
            float x0 = w0[k], x1 = w1[k], x2 = w2[k], x3 = w3[k];
#pragma unroll
            for (int b = 0; b < 8; b++) {
                float h = hs[b][k];
                a[0][b] += x0 * h; a[1][b] += x1 * h; a[2][b] += x2 * h; a[3][b] += x3 * h;
            }
        }
#pragma unroll
        for (int g = 0; g < 4; g++)
#pragma unroll
            for (int b = 0; b < 8; b++) a[g][b] = wsum(a[g][b]);
        if (lane == 0) {
#pragma unroll
            for (int b = 0; b < 8; b++) {
                const float* ex = &g_encx[((size_t)t * 8 + b) * G4_];
                float gi = sigf(a[0][b] + ex[j]);
                float gf = sigf(a[1][b] + ex[H_ + j]);
                float gg = tanhf(a[2][b] + ex[2 * H_ + j]);
                float go = sigf(a[3][b] + ex[3 * H_ + j]);
                float c = gf * g_c[b * H_ + j] + gi * gg;
                g_c[b * H_ + j] = c;
                g_encout[((size_t)t * 8 + b) * H_ + j] = go * tanhf(c);
            }
        }
        grid_bar(125);
    }
}

__global__ __launch_bounds__(256) void dec_emb2(int s) {
    __shared__ float hs[8][H_];
    int tid = threadIdx.x;
    if (s > 0) {
        for (int b = 0; b < 8; b++)
            for (int k = tid; k < H_; k += 256)
                hs[b][k] = g_HS[((size_t)(s - 1) * 8 + b) * H_ + k];
        __syncthreads();
    }
    int w = tid >> 5, lane = tid & 31;
    int j = blockIdx.x * 8 + w;
    float a[8];
#pragma unroll
    for (int b = 0; b < 8; b++) a[b] = 0.f;
    if (s > 0) {
        const float* m = &g_M2[(size_t)j * 1033];
        for (int k = lane; k < H_; k += 32) {
            float mv = m[k];
#pragma unroll
            for (int b = 0; b < 8; b++) a[b] += mv * hs[b][k];
        }
    }
#pragma unroll
    for (int b = 0; b < 8; b++) a[b] = wsum(a[b]);
    if (lane == 0) {
#pragma unroll
        for (int b = 0; b < 8; b++) {
            float v = g_pre[((size_t)s * 8 + b) * H_ + j];
            if (s == 0) v += g_M2[(size_t)j * 1033 + 1024 + b];
            else v += a[b] + g_M2[(size_t)j * 1033 + 1032];
            g_emb[b * H_ + j] = v;
        }
    }
}

__global__ __launch_bounds__(256) void dec_attn2(int s, const float* __restrict__ attn_W,
                                                 const float* __restrict__ attn_b,
                                                 const float* __restrict__ noise2) {
    extern __shared__ float vs[];
    int tid = threadIdx.x;
    for (int b = 0; b < 8; b++) {
        const float* hp = (s == 0) ? &g_encout[((size_t)(T_ - 1) * 8 + b) * H_]
                                   : &g_HS[((size_t)(s - 1) * 8 + b) * H_];
        const float* n2 = noise2 + ((size_t)s * 8 + b) * H_;
        float* vb = vs + b * 3000;
        for (int k = tid; k < H_; k += 256) {
            vb[k] = g_emb[b * H_ + k];
            vb[H_ + k] = hp[k];
            vb[2 * H_ + k] = n2[k];
        }
    }
    __syncthreads();
    int w = tid >> 5, lane = tid & 31;
    int t = blockIdx.x * 8 + w;
    const float* wr = attn_W + (size_t)t * 3 * H_;
    float a[8];
#pragma unroll
    for (int b = 0; b < 8; b++) a[b] = 0.f;
    for (int k = lane; k < 3 * H_; k += 32) {
        float wv = wr[k];
#pragma unroll
        for (int b = 0; b < 8; b++) a[b] += wv * vs[b * 3000 + k];
    }
#pragma unroll
    for (int b = 0; b < 8; b++) a[b] = wsum(a[b]);
    if (lane == 0) {
        float ab = attn_b[t];
#pragma unroll
        for (int b = 0; b < 8; b++) g_logit[b * T_ + t] = a[b] + ab;
    }
}

__global__ void dec_soft() {
    __shared__ float aw[T_];
    __shared__ float red[8];
    int b = blockIdx.x, tid = threadIdx.x;
    int w = tid >> 5, lane = tid & 31;
    float l = (tid < T_) ? g_logit[b * T_ + tid] : -1e30f;
    float m = l;
#pragma unroll
    for (int o = 16; o; o >>= 1) m = fmaxf(m, __shfl_xor_sync(0xffffffffu, m, o));
    if (lane == 0) red[w] = m;
    __syncthreads();
    if (tid == 0) {
        float mm = red[0];
        for (int i = 1; i < 8; i++) mm = fmaxf(mm, red[i]);
        red[0] = mm;
    }
    __syncthreads();
    float mx = red[0];
    float e = (tid < T_) ? expf(l - mx) : 0.f;
    float ss = wsum(e);
    __syncthreads();
    if (lane == 0) red[w] = ss;
    __syncthreads();
    if (tid == 0) {
        float t2 = 0;
        for (int i = 0; i < 8; i++) t2 += red[i];
        red[0] = t2;
    }
    __syncthreads();
    float inv = 1.f / red[0];
    if (tid < T_) aw[tid] = e * inv;
    __syncthreads();
    for (int i = tid; i < H_; i += 256) {
        float acc = 0.f;
#pragma unroll 4
        for (int t = 0; t < T_; t++) acc += aw[t] * g_encout[((size_t)t * 8 + b) * H_ + i];
        g_applied[b * H_ + i] = acc;
    }
}

__global__ __launch_bounds__(256) void dec_comb2(const float* __restrict__ comb_W,
                                                 const float* __restrict__ comb_b) {
    extern __shared__ float sm[];
    float* es = sm;
    float* ap = sm + 8 * H_;
    int tid = threadIdx.x;
    for (int b = 0; b < 8; b++)
        for (int k = tid; k < H_; k += 256) {
            es[b * H_ + k] = g_emb[b * H_ + k];
            ap[b * H_ + k] = g_applied[b * H_ + k];
        }
    __syncthreads();
    int w = tid >> 5, lane = tid & 31;
    int i = blockIdx.x * 8 + w;
    const float* wr = comb_W + (size_t)i * 2 * H_;
    float a[8];
#pragma unroll
    for (int b = 0; b < 8; b++) a[b] = 0.f;
    for (int k = lane; k < H_; k += 32) {
        float w1 = wr[k], w2 = wr[H_ + k];
#pragma unroll
        for (int b = 0; b < 8; b++) a[b] += es[b * H_ + k] * w1 + ap[b * H_ + k] * w2;
    }
#pragma unroll
    for (int b = 0; b < 8; b++) a[b] = wsum(a[b]);
    if (lane == 0) {
        float cb = comb_b[i];
#pragma unroll
        for (int b = 0; b < 8; b++) g_comb[b * H_ + i] = fmaxf(a[b] + cb, 0.f);
    }
}

__global__ __launch_bounds__(256) void dec_lstm2(int s, const float* __restrict__ Wih,
                                                 const float* __restrict__ Whh,
                                                 const float* __restrict__ bih,
                                                 const float* __restrict__ bhh) {
    extern __shared__ float sm[];
    float* xs = sm;
    float* hs = sm + 8 * H_;
    int tid = threadIdx.x;
    for (int b = 0; b < 8; b++) {
        const float* hp = (s == 0) ? &g_encout[((size_t)(T_ - 1) * 8 + b) * H_]
                                   : &g_HS[((size_t)(s - 1) * 8 + b) * H_];
        for (int k = tid; k < H_; k += 256) {
            xs[b * H_ + k] = g_comb[b * H_ + k];
            hs[b * H_ + k] = hp[k];
        }
    }
    __syncthreads();
    int w = tid >> 5, lane = tid & 31;
    int j = blockIdx.x * 8 + w;
    const float* wi0 = Wih + (size_t)(0 * H_ + j) * H_;
    const float* wi1 = Wih + (size_t)(1 * H_ + j) * H_;
    const float* wi2 = Wih + (size_t)(2 * H_ + j) * H_;
    const float* wi3 = Wih + (size_t)(3 * H_ + j) * H_;
    const float* wh0 = Whh + (size_t)(0 * H_ + j) * H_;
    const float* wh1 = Whh + (size_t)(1 * H_ + j) * H_;
    const float* wh2 = Whh + (size_t)(2 * H_ + j) * H_;
    const float* wh3 = Whh + (size_t)(3 * H_ + j) * H_;
    float a[4][8];
#pragma unroll
    for (int g = 0; g < 4; g++)
#pragma unroll
        for (int b = 0; b < 8; b++) a[g][b] = 0.f;
    for (int k = lane; k < H_; k += 32) {
        float i0 = wi0[k], i1 = wi1[k], i2 = wi2[k], i3 = wi3[k];
        float h0 = wh0[k], h1 = wh1[k], h2 = wh2[k], h3 = wh3[k];
#pragma unroll
        for (int b = 0; b < 8; b++) {
            float x = xs[b * H_ + k], h = hs[b * H_ + k];
            a[0][b] += i0 * x + h0 * h;
            a[1][b] += i1 * x + h1 * h;
            a[2][b] += i2 * x + h2 * h;
            a[3][b] += i3 * x + h3 * h;
        }
    }
#pragma unroll
    for (int g = 0; g < 4; g++)
#pragma unroll
        for (int b = 0; b < 8; b++) a[g][b] = wsum(a[g][b]);
    if (lane == 0) {
        float b0 = bih[j] + bhh[j];
        float b1 = bih[H_ + j] + bhh[H_ + j];
        float b2 = bih[2 * H_ + j] + bhh[2 * H_ + j];
        float b3 = bih[3 * H_ + j] + bhh[3 * H_ + j];
#pragma unroll
        for (int b = 0; b < 8; b++) {
            float gi = sigf(a[0][b] + b0);
            float gf = sigf(a[1][b] + b1);
            float gg = tanhf(a[2][b] + b2);
            float go = sigf(a[3][b] + b3);
            float c = gf * g_c[b * H_ + j] + gi * gg;
            g_c[b * H_ + j] = c;
            g_HS[((size_t)s * 8 + b) * H_ + j] = go * tanhf(c);
        }
    }
}

// ---------------- host: tensormap building ----------------
typedef CUresult (*EncFn)(CUtensorMap*, CUtensorMapDataType, cuuint32_t, void*,
                          const cuuint64_t*, const cuuint64_t*, const cuuint32_t*,
                          const cuuint32_t*, CUtensorMapInterleave, CUtensorMapSwizzle,
                          CUtensorMapL2promotion, CUtensorMapFloatOOBfill);
static EncFn enc_fn() {
    static EncFn fn = nullptr;
    if (!fn) {
        void* p = nullptr;
        cudaDriverEntryPointQueryResult st;
        cudaError_t e = cudaGetDriverEntryPoint("cuTensorMapEncodeTiled", &p,
                                                cudaEnableDefault, &st);
        if (e == cudaSuccess && st == cudaDriverEntryPointSuccess) fn = (EncFn)p;
    }
    return fn;
}
static void mkmap(CUtensorMap* m, void* ptr, uint64_t kpad, uint64_t rows, uint32_t boxRows) {
    cuuint64_t dims[2] = {kpad, rows};
    cuuint64_t strides[1] = {kpad * 2};
    cuuint32_t box[2] = {64u, boxRows};
    cuuint32_t es[2] = {1u, 1u};
    EncFn f = enc_fn();
    if (!f) return;
    f(m, CU_TENSOR_MAP_DATA_TYPE_BFLOAT16, 2, ptr, dims, strides, box, es,
      CU_TENSOR_MAP_INTERLEAVE_NONE, CU_TENSOR_MAP_SWIZZLE_128B,
      CU_TENSOR_MAP_L2_PROMOTION_L2_128B, CU_TENSOR_MAP_FLOAT_OOB_FILL_NONE);
}

// ---------------- launch ----------------
extern "C" void kernel_launch(void* const* d_in, const int* in_sizes, int n_in,
                              void* d_out, int out_size) {
    const float* input   = (const float*)d_in[0];
    const float* noise1  = (const float*)d_in[2];
    const float* noise2  = (const float*)d_in[3];
    const float* initdec = (const float*)d_in[4];
    const float* eWih = (const float*)d_in[5];
    const float* eWhh = (const float*)d_in[6];
    const float* ebih = (const float*)d_in[7];
    const float* ebhh = (const float*)d_in[8];
    const float* dWih = (const float*)d_in[9];
    const float* dWhh = (const float*)d_in[10];
    const float* dbih = (const float*)d_in[11];
    const float* dbhh = (const float*)d_in[12];
    const float* embW = (const float*)d_in[13];
    const float* embb = (const float*)d_in[14];
    const float* attnW = (const float*)d_in[15];
    const float* attnb = (const float*)d_in[16];
    const float* combW = (const float*)d_in[17];
    const float* combb = (const float*)d_in[18];
    const float* outW = (const float*)d_in[19];
    const float* outb = (const float*)d_in[20];
    float* out = (float*)d_out;

    cudaFuncSetAttribute(mma_gemm_tma, cudaFuncAttributeMaxDynamicSharedMemorySize, GSMEM);
    cudaFuncSetAttribute(dec_attn2, cudaFuncAttributeMaxDynamicSharedMemorySize, 96000);
    cudaFuncSetAttribute(dec_comb2, cudaFuncAttributeMaxDynamicSharedMemorySize, 64000);
    cudaFuncSetAttribute(dec_lstm2, cudaFuncAttributeMaxDynamicSharedMemorySize, 64000);

    float *p_encx, *p_pre, *p_HS, *p_M2, *p_part;
    cudaGetSymbolAddress((void**)&p_encx, g_encx);
    cudaGetSymbolAddress((void**)&p_pre, g_pre);
    cudaGetSymbolAddress((void**)&p_HS, g_HS);
    cudaGetSymbolAddress((void**)&p_M2, g_M2);
    cudaGetSymbolAddress((void**)&p_part, g_part);
    __nv_bfloat16 *pAx_h, *pAx_l, *pWih_h, *pWih_l, *pEmb1_h, *pEmb1_l, *pB2_h, *pB2_l;
    __nv_bfloat16 *pN1_h, *pN1_l, *pEmb2_h, *pEmb2_l, *pOutW_h, *pOutW_l, *pHS_h, *pHS_l;
    cudaGetSymbolAddress((void**)&pAx_h, cAx_h);   cudaGetSymbolAddress((void**)&pAx_l, cAx_l);
    cudaGetSymbolAddress((void**)&pWih_h, cWih_h); cudaGetSymbolAddress((void**)&pWih_l, cWih_l);
    cudaGetSymbolAddress((void**)&pEmb1_h, cEmb1_h); cudaGetSymbolAddress((void**)&pEmb1_l, cEmb1_l);
    cudaGetSymbolAddress((void**)&pB2_h, cB2_h);   cudaGetSymbolAddress((void**)&pB2_l, cB2_l);
    cudaGetSymbolAddress((void**)&pN1_h, cN1_h);   cudaGetSymbolAddress((void**)&pN1_l, cN1_l);
    cudaGetSymbolAddress((void**)&pEmb2_h, cEmb2_h); cudaGetSymbolAddress((void**)&pEmb2_l, cEmb2_l);
    cudaGetSymbolAddress((void**)&pOutW_h, cOutW_h); cudaGetSymbolAddress((void**)&pOutW_l, cOutW_l);
    cudaGetSymbolAddress((void**)&pHS_h, cHS_h);   cudaGetSymbolAddress((void**)&pHS_l, cHS_l);

    CUtensorMap mAxh, mAxl, mWihh, mWihl, mE1h, mE1l, mB2h, mB2l;
    CUtensorMap mN1h, mN1l, mE2h, mE2l, mOWh, mOWl, mHSh, mHSl;
    mkmap(&mAxh, pAx_h, KP1, 1024, 128);   mkmap(&mAxl, pAx_l, KP1, 1024, 128);
    mkmap(&mWihh, pWih_h, KP1, 4000, 256); mkmap(&mWihl, pWih_l, KP1, 4000, 256);
    mkmap(&mE1h, pEmb1_h, KP1, 1000, 128); mkmap(&mE1l, pEmb1_l, KP1, 1000, 128);
    mkmap(&mB2h, pB2_h, KP1, 1033, 256);   mkmap(&mB2l, pB2_l, KP1, 1033, 256);
    mkmap(&mN1h, pN1_h, KP3, 512, 128);    mkmap(&mN1l, pN1_l, KP3, 512, 128);
    mkmap(&mE2h, pEmb2_h, KP3, 1000, 256); mkmap(&mE2l, pEmb2_l, KP3, 1000, 256);
    mkmap(&mOWh, pOutW_h, KP6, 30522, 256); mkmap(&mOWl, pOutW_l, KP6, 30522, 256);
    mkmap(&mHSh, pHS_h, KP6, 512, 128);    mkmap(&mHSl, pHS_l, KP6, 512, 128);

    int g1 = (KP1 / 8 + 255) / 256;
    int g3 = (KP3 / 8 + 255) / 256;
    int g6 = (KP6 / 8 + 255) / 256;

    // my-index 3 = GEMM1 (ncu +2 offset lands here)
    conv_pair8<<<dim3(g1, 1024), 256>>>(input, E_, 1, pAx_h, pAx_l, E_, KP1);          // 0
    conv_pair8<<<dim3(g1, 4000), 256>>>(eWih, E_, 0, pWih_h, pWih_l, E_, KP1);         // 1
    zero_c<<<(B_ * H_ + 255) / 256, 256>>>();                                          // 2
    mma_gemm_tma<<<dim3(16, 8, 1), 256, GSMEM>>>(mAxh, mAxl, mWihh, mWihl,             // 3: GEMM1
        ebih, ebhh, p_encx, 1024, G4_, G4_, KP1 / 64, KP1 / 64, 0, 0);

    conv_pair8<<<dim3(g1, 1000), 256>>>(embW, EN_, 0, pEmb1_h, pEmb1_l, E_, KP1);
    conv_trans<<<dim3(954, 32), dim3(32, 8)>>>(outW, E_, H_, pB2_h, pB2_l, H_, KP1);
    conv_pair8<<<dim3(g3, 1000), 256>>>(embW + E_, EN_, 0, pEmb2_h, pEmb2_l, NZ_, KP3);
    conv_pair8<<<dim3(g3, 512), 256>>>(noise1, NZ_, 0, pN1_h, pN1_l, NZ_, KP3);
    conv_pair8<<<dim3(g6, 30522), 256>>>(outW, H_, 0, pOutW_h, pOutW_l, H_, KP6);

    // E0 / bvec columns of g_M2 — exact fp32 SIMT (replaces GEMM2's 5th N-tile)
    e0bvec<<<125, 256>>>(embW, initdec, outb);

    // GEMM2: x=4 -> N=1024 (128 CTAs = 1 wave), split-K=4, reduce into 1033-stride rows
    mma_gemm_tma<<<dim3(4, 8, 4), 256, GSMEM>>>(mE1h, mE1l, mB2h, mB2l,
        nullptr, nullptr, p_part, H_, 1024, 1024, KP1 / 64, 120, (long long)H_ * 1024, 0);
    reduce_ld<<<(H_ * 1024 + 255) / 256, 256>>>(p_part, p_M2, H_, 1024, 1033, 4);

    // GEMM3 split-K=8 (128 CTAs, 1 wave)
    mma_gemm_tma<<<dim3(4, 4, 8), 256, GSMEM>>>(mN1h, mN1l, mE2h, mE2l,
        nullptr, nullptr, p_part, S_ * B_, H_, H_, KP3 / 64, 20, (long long)S_ * B_ * H_, 0);
    reduce_parts<<<(S_ * B_ * H_ + 255) / 256, 256>>>(p_part, p_pre, embb, S_ * B_, H_, 8);

    // encoder scan (persistent)
    enc_scan<<<125, 256>>>(eWhh);

    // decoder scan (per-step launches — proven best config)
    for (int s = 0; s < S_; s++) {
        dec_emb2<<<125, 256>>>(s);
        dec_attn2<<<16, 256, 96000>>>(s, attnW, attnb, noise2);
        dec_soft<<<B_, 256>>>();
        dec_comb2<<<125, 256, 64000>>>(combW, combb);
        dec_lstm2<<<125, 256, 64000>>>(s, dWih, dWhh, dbih, dbhh);
    }

    // final output GEMM
    conv_pair8<<<dim3(g6, 512), 256>>>(p_HS, H_, 0, pHS_h, pHS_l, H_, KP6);
    mma_gemm_tma<<<dim3(120, 4, 1), 256, GSMEM>>>(mHSh, mHSl, mOWh, mOWl,
        outb, nullptr, out, S_ * B_, E_, E_, KP6 / 64, KP6 / 64, 0, 0);
}

// round 17
// speedup vs baseline: 1.5573x; 1.1710x over previous
#include <cuda_runtime.h>
#include <cuda.h>
#include <cuda_fp16.h>
#include <math.h>
#include <stdint.h>

#define B_ 8
#define T_ 128
#define E_ 30522
#define H_ 1000
#define S_ 64
#define NZ_ 10000
#define G4_ 4000
#define EN_ 40522

#define KP1 30528
#define KP3 10048
#define KP6 1024

// ---------------- fp16 operand buffers (zero-init; pads stay zero) ----------------
__device__ __align__(128) __half cAx[(size_t)1024 * KP1];
__device__ __align__(128) __half cWih[(size_t)4096 * KP1];
__device__ __align__(128) __half cEmb1[(size_t)1024 * KP1];
__device__ __align__(128) __half cB2[(size_t)1280 * KP1];
__device__ __align__(128) __half cN1[(size_t)512 * KP3];
__device__ __align__(128) __half cEmb2[(size_t)1024 * KP3];
__device__ __align__(128) __half cOutW[(size_t)30720 * KP6];
__device__ __align__(128) __half cHS[(size_t)512 * KP6];

// ---------------- fp32 scratch ----------------
__device__ float g_encx[(size_t)T_ * B_ * G4_];
__device__ float g_M2[(size_t)H_ * 1033];
__device__ float g_pre[S_ * B_ * H_];
__device__ float g_part[(size_t)8 * 1033 * 1000];
__device__ float g_encout[(size_t)T_ * B_ * H_];
__device__ float g_c[B_ * H_];
__device__ float g_emb[B_ * H_];
__device__ float g_logit[B_ * T_];
__device__ float g_applied[B_ * H_];
__device__ float g_comb[B_ * H_];
__device__ float g_HS[(size_t)S_ * B_ * H_];

__device__ unsigned g_barCnt = 0;
__device__ volatile unsigned g_barPhase = 0;

// ---------------- helpers ----------------
__device__ __forceinline__ float wsum(float v) {
#pragma unroll
    for (int o = 16; o; o >>= 1) v += __shfl_xor_sync(0xffffffffu, v, o);
    return v;
}
__device__ __forceinline__ float sigf(float x) { return 1.f / (1.f + expf(-x)); }
__device__ __forceinline__ uint32_t smem_u32(const void* p) {
    uint32_t a;
    asm("{ .reg .u64 t; cvta.to.shared.u64 t, %1; cvt.u32.u64 %0, t; }" : "=r"(a) : "l"(p));
    return a;
}
#define MBAR_INIT(a, n) asm volatile("mbarrier.init.shared.b64 [%0], %1;" :: "r"(a), "r"(n) : "memory")
#define MBAR_EXPECT_TX(a, b) asm volatile("mbarrier.arrive.expect_tx.shared.b64 _, [%0], %1;" :: "r"(a), "r"(b) : "memory")
#define MBAR_WAIT(a, par) do { \
    asm volatile("{\n\t.reg .pred P1;\n\tWL_%=:\n\t" \
        "mbarrier.try_wait.parity.acquire.cta.shared::cta.b64 P1, [%0], %1, 0x989680;\n\t" \
        "@P1 bra.uni WD_%=;\n\tbra.uni WL_%=;\n\tWD_%=:\n\t}" \
        :: "r"(a), "r"(par) : "memory"); } while (0)
#define FENCE_ASYNC() asm volatile("fence.proxy.async.shared::cta;" ::: "memory")
#define TMA2D(dst, map, cx, cy, mbar) \
    asm volatile("cp.async.bulk.tensor.2d.shared::cta.global.tile.mbarrier::complete_tx::bytes " \
                 "[%0], [%1, {%2, %3}], [%4];" \
                 :: "r"(dst), "l"(map), "r"(cx), "r"(cy), "r"(mbar) : "memory")
#define LDSM4(r0, r1, r2, r3, a) \
    asm volatile("ldmatrix.sync.aligned.m8n8.x4.shared.b16 {%0,%1,%2,%3}, [%4];" \
                 : "=r"(r0), "=r"(r1), "=r"(r2), "=r"(r3) : "r"(a))
__device__ __forceinline__ void mma16(float* d, const uint32_t* a, uint32_t b0, uint32_t b1) {
    asm volatile(
        "mma.sync.aligned.m16n8k16.row.col.f32.f16.f16.f32 "
        "{%0,%1,%2,%3}, {%4,%5,%6,%7}, {%8,%9}, {%0,%1,%2,%3};"
        : "+f"(d[0]), "+f"(d[1]), "+f"(d[2]), "+f"(d[3])
        : "r"(a[0]), "r"(a[1]), "r"(a[2]), "r"(a[3]), "r"(b0), "r"(b1));
}

__device__ __forceinline__ void grid_bar(int nCtas) {
    __threadfence();
    __syncthreads();
    if (threadIdx.x == 0) {
        unsigned ph = g_barPhase;
        if (atomicAdd(&g_barCnt, 1u) == (unsigned)(nCtas - 1)) {
            atomicExch(&g_barCnt, 0u);
            __threadfence();
            g_barPhase = ph + 1;
        } else {
            while (g_barPhase == ph) { __nanosleep(64); }
        }
        __threadfence();
    }
    __syncthreads();
}

// ---------------- TMA + mma.sync GEMM, single-term fp16 ----------------
// Tile M=128, N=256, K-chunk 64. Stage: A 16K | B 32K = 48K; 2 stages.
#define STG_B 49152
#define STG_TX 49152u
#define GSMEM (1024 + 2 * STG_B)

__global__ __launch_bounds__(256) void mma_gemm_tma(
    const __grid_constant__ CUtensorMap mA, const __grid_constant__ CUtensorMap mB,
    const float* __restrict__ bias1, const float* __restrict__ bias2,
    float* __restrict__ C, int M, int N, int ldc,
    int nch, int cpp, long long partStride, int mOff)
{
    extern __shared__ __align__(128) char smem[];
    __shared__ __align__(16) uint64_t mbars[2];
    uint32_t sb = (smem_u32(smem) + 1023u) & ~1023u;
    uint32_t mb0 = smem_u32(&mbars[0]);
    int tid = threadIdx.x, wid = tid >> 5, lane = tid & 31;
    int moff = (wid >> 1) * 32, noff = (wid & 1) * 128;
    int mBase = mOff + blockIdx.y * 128, nBase = blockIdx.x * 256;
    int z = blockIdx.z;
    int c0 = z * cpp;
    int c1 = c0 + cpp; if (c1 > nch) c1 = nch;
    float* Cw = C + (size_t)z * (size_t)partStride;

    if (tid == 0) {
        MBAR_INIT(mb0, 1);
        MBAR_INIT(mb0 + 8, 1);
        FENCE_ASYNC();
    }
    __syncthreads();

    float acc[2][16][4];
#pragma unroll
    for (int i = 0; i < 2; i++)
#pragma unroll
        for (int j = 0; j < 16; j++)
#pragma unroll
            for (int c = 0; c < 4; c++) acc[i][j][c] = 0.f;

    auto issue = [&](int st, int c) {
        uint32_t s0 = sb + st * STG_B;
        uint32_t mb = mb0 + st * 8;
        int kx = c * 64;
        MBAR_EXPECT_TX(mb, STG_TX);
        TMA2D(s0,          &mA, kx, mBase, mb);
        TMA2D(s0 + 16384,  &mB, kx, nBase, mb);
    };

    if (tid == 0) {
        issue(0, c0);
        if (c0 + 1 < c1) issue(1, c0 + 1);
    }

    int arow0 = moff + (lane & 15);
    int ahalf = lane >> 4;
    int bsel = (lane & 7) | (((lane >> 4) & 1) << 3);
    int bhalf = (lane >> 3) & 1;

    for (int c = c0; c < c1; c++) {
        int st = (c - c0) & 1;
        int ph = ((c - c0) >> 1) & 1;
        MBAR_WAIT(mb0 + st * 8, ph);

        uint32_t s0 = sb + st * STG_B;
        uint32_t Ab = s0, Bb = s0 + 16384;
#pragma unroll
        for (int h = 0; h < 4; h++) {
            uint32_t aH0[4], aH1[4];
            {
                int r0 = arow0, r1 = arow0 + 16;
                uint32_t c0a = ((uint32_t)((2 * h + ahalf) ^ (r0 & 7))) << 4;
                uint32_t c1a = ((uint32_t)((2 * h + ahalf) ^ (r1 & 7))) << 4;
                LDSM4(aH0[0], aH0[1], aH0[2], aH0[3], Ab + r0 * 128 + c0a);
                LDSM4(aH1[0], aH1[1], aH1[2], aH1[3], Ab + r1 * 128 + c1a);
            }
#pragma unroll
            for (int p = 0; p < 8; p++) {
                int br = noff + p * 16 + bsel;
                uint32_t bc = ((uint32_t)((2 * h + bhalf) ^ (br & 7))) << 4;
                uint32_t bH[4];
                LDSM4(bH[0], bH[1], bH[2], bH[3], Bb + br * 128 + bc);
                mma16(acc[0][2 * p],     aH0, bH[0], bH[1]);
                mma16(acc[0][2 * p + 1], aH0, bH[2], bH[3]);
                mma16(acc[1][2 * p],     aH1, bH[0], bH[1]);
                mma16(acc[1][2 * p + 1], aH1, bH[2], bH[3]);
            }
        }
        __syncthreads();
        if (tid == 0 && c + 2 < c1) issue(st, c + 2);
    }

    int gid = lane >> 2, tig = lane & 3;
#pragma unroll
    for (int mt = 0; mt < 2; mt++)
#pragma unroll
        for (int nt = 0; nt < 16; nt++)
#pragma unroll
            for (int cc = 0; cc < 4; cc++) {
                int row = mBase + moff + mt * 16 + gid + ((cc >> 1) ? 8 : 0);
                int col = nBase + noff + nt * 8 + tig * 2 + (cc & 1);
                if (row < M && col < N) {
                    float v = acc[mt][nt][cc];
                    if (bias1) v += bias1[col];
                    if (bias2) v += bias2[col];
                    Cw[(size_t)row * ldc + col] = v;
                }
            }
}

// ---------------- split-K reduction ----------------
__global__ void reduce_parts(const float* __restrict__ part, float* __restrict__ dst,
                             const float* __restrict__ bias, int M, int N, int nparts) {
    int i = blockIdx.x * 256 + threadIdx.x;
    if (i >= M * N) return;
    size_t stride = (size_t)M * N;
    float s = 0.f;
    for (int z = 0; z < nparts; z++) s += part[z * stride + i];
    if (bias) s += bias[i % N];
    dst[i] = s;
}

// ---------------- conversion kernels (fp16, 8 elems/thread) ----------------
__global__ void conv_h8(const float* __restrict__ src, int srcLd, int encmap,
                        __half* __restrict__ dh, int K, int Kpad) {
    int k0 = (blockIdx.x * 256 + threadIdx.x) * 8;
    int r = blockIdx.y;
    if (k0 >= Kpad) return;
    size_t so;
    if (encmap) { int t = r >> 3, b = r & 7; so = ((size_t)b * T_ + t) * (size_t)srcLd; }
    else so = (size_t)r * (size_t)srcLd;
    uint32_t hw[4];
#pragma unroll
    for (int jj = 0; jj < 4; jj++) {
        float v0 = (k0 + 2 * jj     < K) ? src[so + k0 + 2 * jj]     : 0.f;
        float v1 = (k0 + 2 * jj + 1 < K) ? src[so + k0 + 2 * jj + 1] : 0.f;
        __half h0 = __float2half_rn(v0);
        __half h1 = __float2half_rn(v1);
        hw[jj] = ((uint32_t)__half_as_ushort(h1) << 16) | __half_as_ushort(h0);
    }
    *reinterpret_cast<uint4*>(dh + (size_t)r * Kpad + k0) = make_uint4(hw[0], hw[1], hw[2], hw[3]);
}

__global__ void conv_trans(const float* __restrict__ src, int srcRows, int srcCols,
                           __half* __restrict__ dh, int dstRows, int Kpad) {
    __shared__ float t[32][33];
    int e0 = blockIdx.x * 32, h0 = blockIdx.y * 32;
    int tx = threadIdx.x, ty = threadIdx.y;
    for (int i = ty; i < 32; i += 8) {
        int e = e0 + i, h = h0 + tx;
        t[i][tx] = (e < srcRows && h < srcCols) ? src[(size_t)e * srcCols + h] : 0.f;
    }
    __syncthreads();
    for (int i = ty; i < 32; i += 8) {
        int h = h0 + i, e = e0 + tx;
        if (h < dstRows && e < Kpad)
            dh[(size_t)h * Kpad + e] = __float2half_rn(t[tx][i]);
    }
}

// ---------------- encoder (persistent) + decoder (per-step launches) ----------------
__global__ void zero_c() {
    int i = blockIdx.x * blockDim.x + threadIdx.x;
    if (i < B_ * H_) g_c[i] = 0.f;
}

__global__ __launch_bounds__(256) void enc_scan(const float* __restrict__ Whh) {
    __shared__ float hs[8][H_];
    int tid = threadIdx.x;
    int w = tid >> 5, lane = tid & 31;
    int j = blockIdx.x * 8 + w;
    const float* w0 = Whh + (size_t)(0 * H_ + j) * H_;
    const float* w1 = Whh + (size_t)(1 * H_ + j) * H_;
    const float* w2 = Whh + (size_t)(2 * H_ + j) * H_;
    const float* w3 = Whh + (size_t)(3 * H_ + j) * H_;
    for (int t = 0; t < T_; t++) {
        for (int b = 0; b < 8; b++)
            for (int k = tid; k < H_; k += 256)
                hs[b][k] = (t == 0) ? 0.f : g_encout[((size_t)(t - 1) * 8 + b) * H_ + k];
        __syncthreads();
        float a[4][8];
#pragma unroll
        for (int g = 0; g < 4; g++)
#pragma unroll
            for (int b = 0; b < 8; b++) a[g][b] = 0.f;
        for (int k = lane; k < H_; k += 32) {
            float x0 = w0[k], x1 = w1[k], x2 = w2[k], x3 = w3[k];
#pragma unroll
            for (int b = 0; b < 8; b++) {
                float h = hs[b][k];
                a[0][b] += x0 * h; a[1][b] += x1 * h; a[2][b] += x2 * h; a[3][b] += x3 * h;
            }
        }
#pragma unroll
        for (int g = 0; g < 4; g++)
#pragma unroll
            for (int b = 0; b < 8; b++) a[g][b] = wsum(a[g][b]);
        if (lane == 0) {
#pragma unroll
            for (int b = 0; b < 8; b++) {
                const float* ex = &g_encx[((size_t)t * 8 + b) * G4_];
                float gi = sigf(a[0][b] + ex[j]);
                float gf = sigf(a[1][b] + ex[H_ + j]);
                float gg = tanhf(a[2][b] + ex[2 * H_ + j]);
                float go = sigf(a[3][b] + ex[3 * H_ + j]);
                float c = gf * g_c[b * H_ + j] + gi * gg;
                g_c[b * H_ + j] = c;
                g_encout[((size_t)t * 8 + b) * H_ + j] = go * tanhf(c);
            }
        }
        grid_bar(125);
    }
}

__global__ __launch_bounds__(256) void dec_emb2(int s) {
    __shared__ float hs[8][H_];
    int tid = threadIdx.x;
    if (s > 0) {
        for (int b = 0; b < 8; b++)
            for (int k = tid; k < H_; k += 256)
                hs[b][k] = g_HS[((size_t)(s - 1) * 8 + b) * H_ + k];
        __syncthreads();
    }
    int w = tid >> 5, lane = tid & 31;
    int j = blockIdx.x * 8 + w;
    float a[8];
#pragma unroll
    for (int b = 0; b < 8; b++) a[b] = 0.f;
    if (s > 0) {
        const float* m = &g_M2[(size_t)j * 1033];
        for (int k = lane; k < H_; k += 32) {
            float mv = m[k];
#pragma unroll
            for (int b = 0; b < 8; b++) a[b] += mv * hs[b][k];
        }
    }
#pragma unroll
    for (int b = 0; b < 8; b++) a[b] = wsum(a[b]);
    if (lane == 0) {
#pragma unroll
        for (int b = 0; b < 8; b++) {
            float v = g_pre[((size_t)s * 8 + b) * H_ + j];
            if (s == 0) v += g_M2[(size_t)j * 1033 + 1024 + b];
            else v += a[b] + g_M2[(size_t)j * 1033 + 1032];
            g_emb[b * H_ + j] = v;
        }
    }
}

__global__ __launch_bounds__(256) void dec_attn2(int s, const float* __restrict__ attn_W,
                                                 const float* __restrict__ attn_b,
                                                 const float* __restrict__ noise2) {
    extern __shared__ float vs[];
    int tid = threadIdx.x;
    for (int b = 0; b < 8; b++) {
        const float* hp = (s == 0) ? &g_encout[((size_t)(T_ - 1) * 8 + b) * H_]
                                   : &g_HS[((size_t)(s - 1) * 8 + b) * H_];
        const float* n2 = noise2 + ((size_t)s * 8 + b) * H_;
        float* vb = vs + b * 3000;
        for (int k = tid; k < H_; k += 256) {
            vb[k] = g_emb[b * H_ + k];
            vb[H_ + k] = hp[k];
            vb[2 * H_ + k] = n2[k];
        }
    }
    __syncthreads();
    int w = tid >> 5, lane = tid & 31;
    int t = blockIdx.x * 8 + w;
    const float* wr = attn_W + (size_t)t * 3 * H_;
    float a[8];
#pragma unroll
    for (int b = 0; b < 8; b++) a[b] = 0.f;
    for (int k = lane; k < 3 * H_; k += 32) {
        float wv = wr[k];
#pragma unroll
        for (int b = 0; b < 8; b++) a[b] += wv * vs[b * 3000 + k];
    }
#pragma unroll
    for (int b = 0; b < 8; b++) a[b] = wsum(a[b]);
    if (lane == 0) {
        float ab = attn_b[t];
#pragma unroll
        for (int b = 0; b < 8; b++) g_logit[b * T_ + t] = a[b] + ab;
    }
}

__global__ void dec_soft() {
    __shared__ float aw[T_];
    __shared__ float red[8];
    int b = blockIdx.x, tid = threadIdx.x;
    int w = tid >> 5, lane = tid & 31;
    float l = (tid < T_) ? g_logit[b * T_ + tid] : -1e30f;
    float m = l;
#pragma unroll
    for (int o = 16; o; o >>= 1) m = fmaxf(m, __shfl_xor_sync(0xffffffffu, m, o));
    if (lane == 0) red[w] = m;
    __syncthreads();
    if (tid == 0) {
        float mm = red[0];
        for (int i = 1; i < 8; i++) mm = fmaxf(mm, red[i]);
        red[0] = mm;
    }
    __syncthreads();
    float mx = red[0];
    float e = (tid < T_) ? expf(l - mx) : 0.f;
    float ss = wsum(e);
    __syncthreads();
    if (lane == 0) red[w] = ss;
    __syncthreads();
    if (tid == 0) {
        float t2 = 0;
        for (int i = 0; i < 8; i++) t2 += red[i];
        red[0] = t2;
    }
    __syncthreads();
    float inv = 1.f / red[0];
    if (tid < T_) aw[tid] = e * inv;
    __syncthreads();
    for (int i = tid; i < H_; i += 256) {
        float acc = 0.f;
#pragma unroll 4
        for (int t = 0; t < T_; t++) acc += aw[t] * g_encout[((size_t)t * 8 + b) * H_ + i];
        g_applied[b * H_ + i] = acc;
    }
}

__global__ __launch_bounds__(256) void dec_comb2(const float* __restrict__ comb_W,
                                                 const float* __restrict__ comb_b) {
    extern __shared__ float sm[];
    float* es = sm;
    float* ap = sm + 8 * H_;
    int tid = threadIdx.x;
    for (int b = 0; b < 8; b++)
        for (int k = tid; k < H_; k += 256) {
            es[b * H_ + k] = g_emb[b * H_ + k];
            ap[b * H_ + k] = g_applied[b * H_ + k];
        }
    __syncthreads();
    int w = tid >> 5, lane = tid & 31;
    int i = blockIdx.x * 8 + w;
    const float* wr = comb_W + (size_t)i * 2 * H_;
    float a[8];
#pragma unroll
    for (int b = 0; b < 8; b++) a[b] = 0.f;
    for (int k = lane; k < H_; k += 32) {
        float w1 = wr[k], w2 = wr[H_ + k];
#pragma unroll
        for (int b = 0; b < 8; b++) a[b] += es[b * H_ + k] * w1 + ap[b * H_ + k] * w2;
    }
#pragma unroll
    for (int b = 0; b < 8; b++) a[b] = wsum(a[b]);
    if (lane == 0) {
        float cb = comb_b[i];
#pragma unroll
        for (int b = 0; b < 8; b++) g_comb[b * H_ + i] = fmaxf(a[b] + cb, 0.f);
    }
}

__global__ __launch_bounds__(256) void dec_lstm2(int s, const float* __restrict__ Wih,
                                                 const float* __restrict__ Whh,
                                                 const float* __restrict__ bih,
                                                 const float* __restrict__ bhh) {
    extern __shared__ float sm[];
    float* xs = sm;
    float* hs = sm + 8 * H_;
    int tid = threadIdx.x;
    for (int b = 0; b < 8; b++) {
        const float* hp = (s == 0) ? &g_encout[((size_t)(T_ - 1) * 8 + b) * H_]
                                   : &g_HS[((size_t)(s - 1) * 8 + b) * H_];
        for (int k = tid; k < H_; k += 256) {
            xs[b * H_ + k] = g_comb[b * H_ + k];
            hs[b * H_ + k] = hp[k];
        }
    }
    __syncthreads();
    int w = tid >> 5, lane = tid & 31;
    int j = blockIdx.x * 8 + w;
    const float* wi0 = Wih + (size_t)(0 * H_ + j) * H_;
    const float* wi1 = Wih + (size_t)(1 * H_ + j) * H_;
    const float* wi2 = Wih + (size_t)(2 * H_ + j) * H_;
    const float* wi3 = Wih + (size_t)(3 * H_ + j) * H_;
    const float* wh0 = Whh + (size_t)(0 * H_ + j) * H_;
    const float* wh1 = Whh + (size_t)(1 * H_ + j) * H_;
    const float* wh2 = Whh + (size_t)(2 * H_ + j) * H_;
    const float* wh3 = Whh + (size_t)(3 * H_ + j) * H_;
    float a[4][8];
#pragma unroll
    for (int g = 0; g < 4; g++)
#pragma unroll
        for (int b = 0; b < 8; b++) a[g][b] = 0.f;
    for (int k = lane; k < H_; k += 32) {
        float i0 = wi0[k], i1 = wi1[k], i2 = wi2[k], i3 = wi3[k];
        float h0 = wh0[k], h1 = wh1[k], h2 = wh2[k], h3 = wh3[k];
#pragma unroll
        for (int b = 0; b < 8; b++) {
            float x = xs[b * H_ + k], h = hs[b * H_ + k];
            a[0][b] += i0 * x + h0 * h;
            a[1][b] += i1 * x + h1 * h;
            a[2][b] += i2 * x + h2 * h;
            a[3][b] += i3 * x + h3 * h;
        }
    }
#pragma unroll
    for (int g = 0; g < 4; g++)
#pragma unroll
        for (int b = 0; b < 8; b++) a[g][b] = wsum(a[g][b]);
    if (lane == 0) {
        float b0 = bih[j] + bhh[j];
        float b1 = bih[H_ + j] + bhh[H_ + j];
        float b2 = bih[2 * H_ + j] + bhh[2 * H_ + j];
        float b3 = bih[3 * H_ + j] + bhh[3 * H_ + j];
#pragma unroll
        for (int b = 0; b < 8; b++) {
            float gi = sigf(a[0][b] + b0);
            float gf = sigf(a[1][b] + b1);
            float gg = tanhf(a[2][b] + b2);
            float go = sigf(a[3][b] + b3);
            float c = gf * g_c[b * H_ + j] + gi * gg;
            g_c[b * H_ + j] = c;
            g_HS[((size_t)s * 8 + b) * H_ + j] = go * tanhf(c);
        }
    }
}

// ---------------- host: tensormap building ----------------
typedef CUresult (*EncFn)(CUtensorMap*, CUtensorMapDataType, cuuint32_t, void*,
                          const cuuint64_t*, const cuuint64_t*, const cuuint32_t*,
                          const cuuint32_t*, CUtensorMapInterleave, CUtensorMapSwizzle,
                          CUtensorMapL2promotion, CUtensorMapFloatOOBfill);
static EncFn enc_fn() {
    static EncFn fn = nullptr;
    if (!fn) {
        void* p = nullptr;
        cudaDriverEntryPointQueryResult st;
        cudaError_t e = cudaGetDriverEntryPoint("cuTensorMapEncodeTiled", &p,
                                                cudaEnableDefault, &st);
        if (e == cudaSuccess && st == cudaDriverEntryPointSuccess) fn = (EncFn)p;
    }
    return fn;
}
static void mkmap(CUtensorMap* m, void* ptr, uint64_t kpad, uint64_t rows, uint32_t boxRows) {
    cuuint64_t dims[2] = {kpad, rows};
    cuuint64_t strides[1] = {kpad * 2};
    cuuint32_t box[2] = {64u, boxRows};
    cuuint32_t es[2] = {1u, 1u};
    EncFn f = enc_fn();
    if (!f) return;
    f(m, CU_TENSOR_MAP_DATA_TYPE_FLOAT16, 2, ptr, dims, strides, box, es,
      CU_TENSOR_MAP_INTERLEAVE_NONE, CU_TENSOR_MAP_SWIZZLE_128B,
      CU_TENSOR_MAP_L2_PROMOTION_L2_128B, CU_TENSOR_MAP_FLOAT_OOB_FILL_NONE);
}

// ---------------- launch ----------------
extern "C" void kernel_launch(void* const* d_in, const int* in_sizes, int n_in,
                              void* d_out, int out_size) {
    const float* input   = (const float*)d_in[0];
    const float* noise1  = (const float*)d_in[2];
    const float* noise2  = (const float*)d_in[3];
    const float* initdec = (const float*)d_in[4];
    const float* eWih = (const float*)d_in[5];
    const float* eWhh = (const float*)d_in[6];
    const float* ebih = (const float*)d_in[7];
    const float* ebhh = (const float*)d_in[8];
    const float* dWih = (const float*)d_in[9];
    const float* dWhh = (const float*)d_in[10];
    const float* dbih = (const float*)d_in[11];
    const float* dbhh = (const float*)d_in[12];
    const float* embW = (const float*)d_in[13];
    const float* embb = (const float*)d_in[14];
    const float* attnW = (const float*)d_in[15];
    const float* attnb = (const float*)d_in[16];
    const float* combW = (const float*)d_in[17];
    const float* combb = (const float*)d_in[18];
    const float* outW = (const float*)d_in[19];
    const float* outb = (const float*)d_in[20];
    float* out = (float*)d_out;

    cudaFuncSetAttribute(mma_gemm_tma, cudaFuncAttributeMaxDynamicSharedMemorySize, GSMEM);
    cudaFuncSetAttribute(dec_attn2, cudaFuncAttributeMaxDynamicSharedMemorySize, 96000);
    cudaFuncSetAttribute(dec_comb2, cudaFuncAttributeMaxDynamicSharedMemorySize, 64000);
    cudaFuncSetAttribute(dec_lstm2, cudaFuncAttributeMaxDynamicSharedMemorySize, 64000);

    float *p_encx, *p_pre, *p_HS, *p_M2, *p_part;
    cudaGetSymbolAddress((void**)&p_encx, g_encx);
    cudaGetSymbolAddress((void**)&p_pre, g_pre);
    cudaGetSymbolAddress((void**)&p_HS, g_HS);
    cudaGetSymbolAddress((void**)&p_M2, g_M2);
    cudaGetSymbolAddress((void**)&p_part, g_part);
    __half *pAx, *pWih, *pEmb1, *pB2, *pN1, *pEmb2, *pOutW, *pHS;
    cudaGetSymbolAddress((void**)&pAx, cAx);
    cudaGetSymbolAddress((void**)&pWih, cWih);
    cudaGetSymbolAddress((void**)&pEmb1, cEmb1);
    cudaGetSymbolAddress((void**)&pB2, cB2);
    cudaGetSymbolAddress((void**)&pN1, cN1);
    cudaGetSymbolAddress((void**)&pEmb2, cEmb2);
    cudaGetSymbolAddress((void**)&pOutW, cOutW);
    cudaGetSymbolAddress((void**)&pHS, cHS);

    CUtensorMap mAx, mWih, mE1, mB2, mN1, mE2, mOW, mHS;
    mkmap(&mAx, pAx, KP1, 1024, 128);
    mkmap(&mWih, pWih, KP1, 4000, 256);
    mkmap(&mE1, pEmb1, KP1, 1000, 128);
    mkmap(&mB2, pB2, KP1, 1033, 256);
    mkmap(&mN1, pN1, KP3, 512, 128);
    mkmap(&mE2, pEmb2, KP3, 1000, 256);
    mkmap(&mOW, pOutW, KP6, 30522, 256);
    mkmap(&mHS, pHS, KP6, 512, 128);

    int g1 = (KP1 / 8 + 255) / 256;
    int g3 = (KP3 / 8 + 255) / 256;
    int g6 = (KP6 / 8 + 255) / 256;

    // my-index 3 = GEMM1 (ncu +2 offset lands here)
    conv_h8<<<dim3(g1, 1024), 256>>>(input, E_, 1, pAx, E_, KP1);                      // 0
    conv_h8<<<dim3(g1, 4000), 256>>>(eWih, E_, 0, pWih, E_, KP1);                      // 1
    zero_c<<<(B_ * H_ + 255) / 256, 256>>>();                                          // 2
    mma_gemm_tma<<<dim3(16, 8, 1), 256, GSMEM>>>(mAx, mWih,                            // 3: GEMM1
        ebih, ebhh, p_encx, 1024, G4_, G4_, KP1 / 64, KP1 / 64, 0, 0);

    conv_h8<<<dim3(g1, 1000), 256>>>(embW, EN_, 0, pEmb1, E_, KP1);
    conv_trans<<<dim3(954, 32), dim3(32, 8)>>>(outW, E_, H_, pB2, H_, KP1);
    conv_h8<<<dim3(g1, 8), 256>>>(initdec, E_, 0, pB2 + (size_t)1024 * KP1, E_, KP1);
    conv_h8<<<dim3(g1, 1), 256>>>(outb, E_, 0, pB2 + (size_t)1032 * KP1, E_, KP1);
    conv_h8<<<dim3(g3, 1000), 256>>>(embW + E_, EN_, 0, pEmb2, NZ_, KP3);
    conv_h8<<<dim3(g3, 512), 256>>>(noise1, NZ_, 0, pN1, NZ_, KP3);
    conv_h8<<<dim3(g6, 30522), 256>>>(outW, H_, 0, pOutW, H_, KP6);

    // GEMM2 split-K=4
    mma_gemm_tma<<<dim3(5, 8, 4), 256, GSMEM>>>(mE1, mB2,
        nullptr, nullptr, p_part, H_, 1033, 1033, KP1 / 64, 120, (long long)H_ * 1033, 0);
    reduce_parts<<<(H_ * 1033 + 255) / 256, 256>>>(p_part, p_M2, nullptr, H_, 1033, 4);

    // GEMM3 split-K=8
    mma_gemm_tma<<<dim3(4, 4, 8), 256, GSMEM>>>(mN1, mE2,
        nullptr, nullptr, p_part, S_ * B_, H_, H_, KP3 / 64, 20, (long long)S_ * B_ * H_, 0);
    reduce_parts<<<(S_ * B_ * H_ + 255) / 256, 256>>>(p_part, p_pre, embb, S_ * B_, H_, 8);

    // encoder scan (persistent)
    enc_scan<<<125, 256>>>(eWhh);

    // decoder scan (per-step launches — proven best config)
    for (int s = 0; s < S_; s++) {
        dec_emb2<<<125, 256>>>(s);
        dec_attn2<<<16, 256, 96000>>>(s, attnW, attnb, noise2);
        dec_soft<<<B_, 256>>>();
        dec_comb2<<<125, 256, 64000>>>(combW, combb);
        dec_lstm2<<<125, 256, 64000>>>(s, dWih, dWhh, dbih, dbhh);
    }

    // final output GEMM
    conv_h8<<<dim3(g6, 512), 256>>>(p_HS, H_, 0, pHS, H_, KP6);
    mma_gemm_tma<<<dim3(120, 4, 1), 256, GSMEM>>>(mHS, mOW,
        outb, nullptr, out, S_ * B_, E_, E_, KP6 / 64, KP6 / 64, 0, 0);
}